// round 12
// baseline (speedup 1.0000x reference)
#include <cuda_runtime.h>
#include <cuda_bf16.h>
#include <cstddef>
#include <cstdint>

#define NN 100000
#define NE 1600000
#define D1 512      // hidden dim (layer1 out)
#define D2 128      // output dim
#define K1 1024     // input dim
#define NB_SCAN ((NN + 255) / 256)

// ---------------- scratch (static device globals; referenced ONLY from device code) ---
__device__ float4 g_xw1[(size_t)NN * D1 / 4];   // x @ W1, later out1 (post-relu)
__device__ float4 g_agg1[(size_t)NN * D1 / 4];  // layer1 aggregation result
__device__ float4 g_xw2[(size_t)NN * D2 / 4];   // out1 @ W2
__device__ float  g_dinv[NN];
__device__ float  g_ssrc[NN];
__device__ float  g_sdst[NN];
__device__ int    g_row[NE];
__device__ int    g_col[NE];
__device__ int    g_is64;

// CSR (grouped by destination col)
__device__ int    g_cnt[NN];
__device__ int    g_ptr[NN + 1];
__device__ int    g_cur[NN];
__device__ int    g_bsum[NB_SCAN];
__device__ int    g_boff[NB_SCAN];
__device__ int    g_csr_src[NE];
__device__ int    g_csr_eid[NE];
__device__ float  g_wcsr[NE];
__device__ float  g_e2[NE];

// bf16 hi/lo weight splits, [K, N] layout (as in Round 8)
__device__ __nv_bfloat16 g_w1h[(size_t)K1 * D1];
__device__ __nv_bfloat16 g_w1l[(size_t)K1 * D1];
__device__ __nv_bfloat16 g_w2h[(size_t)D1 * D2];
__device__ __nv_bfloat16 g_w2l[(size_t)D1 * D2];

// ---------------- helpers ---------------------------------------------------
__device__ __forceinline__ void split4(float4 v, uint2& ph, uint2& pl) {
    __nv_bfloat16 h0 = __float2bfloat16(v.x);
    __nv_bfloat16 h1 = __float2bfloat16(v.y);
    __nv_bfloat16 h2 = __float2bfloat16(v.z);
    __nv_bfloat16 h3 = __float2bfloat16(v.w);
    __nv_bfloat16 l0 = __float2bfloat16(v.x - __bfloat162float(h0));
    __nv_bfloat16 l1 = __float2bfloat16(v.y - __bfloat162float(h1));
    __nv_bfloat16 l2 = __float2bfloat16(v.z - __bfloat162float(h2));
    __nv_bfloat16 l3 = __float2bfloat16(v.w - __bfloat162float(h3));
    ph.x = ((uint32_t)__bfloat16_as_ushort(h1) << 16) | __bfloat16_as_ushort(h0);
    ph.y = ((uint32_t)__bfloat16_as_ushort(h3) << 16) | __bfloat16_as_ushort(h2);
    pl.x = ((uint32_t)__bfloat16_as_ushort(l1) << 16) | __bfloat16_as_ushort(l0);
    pl.y = ((uint32_t)__bfloat16_as_ushort(l3) << 16) | __bfloat16_as_ushort(l2);
}

// WHICH 1: W1 -> g_w1h/l ; 2: W2 -> g_w2h/l
template <int WHICH>
__global__ void k_split(const float4* __restrict__ src, int n4) {
    int idx = blockIdx.x * blockDim.x + threadIdx.x;
    if (idx >= n4) return;
    __nv_bfloat16* Dh = (WHICH == 1) ? g_w1h : g_w2h;
    __nv_bfloat16* Dl = (WHICH == 1) ? g_w1l : g_w2l;
    uint2 ph, pl;
    split4(src[idx], ph, pl);
    ((uint2*)Dh)[idx] = ph;
    ((uint2*)Dl)[idx] = pl;
}

// ---------------- edge_index dtype detect + convert + histogram ------------
__global__ void k_detect(const int* __restrict__ ei32) {
    if (blockIdx.x != 0 || threadIdx.x != 0) return;
    int is64 = 1;
    for (int i = 1; i < 512; i += 2) {
        if (ei32[i] != 0) { is64 = 0; break; }
    }
    g_is64 = is64;
}

__global__ void k_zero_cnt() {
    int i = blockIdx.x * blockDim.x + threadIdx.x;
    if (i < NN) g_cnt[i] = 0;
}

__global__ void k_convert(const void* __restrict__ ei) {
    int e = blockIdx.x * blockDim.x + threadIdx.x;
    if (e >= NE) return;
    int r, c;
    if (g_is64) {
        const long long* p = (const long long*)ei;
        r = (int)p[e];
        c = (int)p[NE + e];
    } else {
        const int* p = (const int*)ei;
        r = p[e];
        c = p[NE + e];
    }
    g_row[e] = r;
    g_col[e] = c;
    atomicAdd(&g_cnt[c], 1);
}

// ---------------- exclusive scan of g_cnt -> g_ptr --------------------------
__global__ void k_scan_block() {
    __shared__ int sh[256];
    int i = blockIdx.x * 256 + threadIdx.x;
    int v = (i < NN) ? g_cnt[i] : 0;
    sh[threadIdx.x] = v;
    __syncthreads();
    #pragma unroll
    for (int o = 1; o < 256; o <<= 1) {
        int t = (threadIdx.x >= o) ? sh[threadIdx.x - o] : 0;
        __syncthreads();
        sh[threadIdx.x] += t;
        __syncthreads();
    }
    if (i < NN) g_ptr[i] = sh[threadIdx.x] - v;
    if (threadIdx.x == 255) g_bsum[blockIdx.x] = sh[255];
}

__global__ void k_scan_bsum() {
    if (blockIdx.x != 0 || threadIdx.x != 0) return;
    int run = 0;
    for (int b = 0; b < NB_SCAN; b++) {
        g_boff[b] = run;
        run += g_bsum[b];
    }
}

__global__ void k_scan_add() {
    int i = blockIdx.x * blockDim.x + threadIdx.x;
    if (i < NN) {
        int p = g_ptr[i] + g_boff[i >> 8];
        g_ptr[i] = p;
        g_cur[i] = p;
    }
    if (i == 0) g_ptr[NN] = NE;
}

__global__ void k_fill() {
    int e = blockIdx.x * blockDim.x + threadIdx.x;
    if (e >= NE) return;
    int c = g_col[e];
    int pos = atomicAdd(&g_cur[c], 1);
    g_csr_src[pos] = g_row[e];
    g_csr_eid[pos] = e;
}

// ---------------- per-node degree / dinv (atomic-free via CSR) --------------
__global__ void k_deg1(const float* __restrict__ ew) {
    int i = blockIdx.x * blockDim.x + threadIdx.x;
    if (i >= NN) return;
    int s = g_ptr[i], e = g_ptr[i + 1];
    float acc = 0.0f;
    for (int j = s; j < e; j++) acc += ew[g_csr_eid[j]];
    g_dinv[i] = rsqrtf(1.0f + acc);
}

__global__ void k_deg2(const float* __restrict__ bm) {
    int i = blockIdx.x * blockDim.x + threadIdx.x;
    if (i >= NN) return;
    int s = g_ptr[i], e = g_ptr[i + 1];
    float sd = g_sdst[i] + bm[0];
    float acc = 0.0f;
    for (int j = s; j < e; j++) {
        float v = fmaxf(g_ssrc[g_csr_src[j]] + sd, 0.0f);
        g_e2[j] = v;
        acc += v;
    }
    g_dinv[i] = rsqrtf(1.0f + acc);
}

__global__ void k_w1pre(const float* __restrict__ ew) {
    int j = blockIdx.x * blockDim.x + threadIdx.x;
    if (j < NE) g_wcsr[j] = g_dinv[g_csr_src[j]] * ew[g_csr_eid[j]];
}
__global__ void k_w2pre() {
    int j = blockIdx.x * blockDim.x + threadIdx.x;
    if (j < NE) g_wcsr[j] = g_dinv[g_csr_src[j]] * g_e2[j];
}

// ---------------- CSR gather aggregation (no atomics) -----------------------
__global__ void k_gather1() {
    int c = (blockIdx.x * blockDim.x + threadIdx.x) >> 5;
    int lane = threadIdx.x & 31;
    if (c >= NN) return;
    int s = g_ptr[c], e = g_ptr[c + 1];
    float4 a0 = make_float4(0, 0, 0, 0), a1 = a0, a2 = a0, a3 = a0;
    for (int j = s; j < e; j++) {
        int r = g_csr_src[j];
        float w = g_wcsr[j];
        const float4* x = g_xw1 + (size_t)r * 128 + lane;
        float4 v0 = x[0], v1 = x[32], v2 = x[64], v3 = x[96];
        a0.x = fmaf(w, v0.x, a0.x); a0.y = fmaf(w, v0.y, a0.y);
        a0.z = fmaf(w, v0.z, a0.z); a0.w = fmaf(w, v0.w, a0.w);
        a1.x = fmaf(w, v1.x, a1.x); a1.y = fmaf(w, v1.y, a1.y);
        a1.z = fmaf(w, v1.z, a1.z); a1.w = fmaf(w, v1.w, a1.w);
        a2.x = fmaf(w, v2.x, a2.x); a2.y = fmaf(w, v2.y, a2.y);
        a2.z = fmaf(w, v2.z, a2.z); a2.w = fmaf(w, v2.w, a2.w);
        a3.x = fmaf(w, v3.x, a3.x); a3.y = fmaf(w, v3.y, a3.y);
        a3.z = fmaf(w, v3.z, a3.z); a3.w = fmaf(w, v3.w, a3.w);
    }
    float dc = g_dinv[c];
    float ds = dc * dc;
    const float4* xc = g_xw1 + (size_t)c * 128 + lane;
    float4* o = g_agg1 + (size_t)c * 128 + lane;
    float4 s0 = xc[0], s1 = xc[32], s2 = xc[64], s3 = xc[96];
    o[0]  = make_float4(fmaf(dc, a0.x, ds * s0.x), fmaf(dc, a0.y, ds * s0.y),
                        fmaf(dc, a0.z, ds * s0.z), fmaf(dc, a0.w, ds * s0.w));
    o[32] = make_float4(fmaf(dc, a1.x, ds * s1.x), fmaf(dc, a1.y, ds * s1.y),
                        fmaf(dc, a1.z, ds * s1.z), fmaf(dc, a1.w, ds * s1.w));
    o[64] = make_float4(fmaf(dc, a2.x, ds * s2.x), fmaf(dc, a2.y, ds * s2.y),
                        fmaf(dc, a2.z, ds * s2.z), fmaf(dc, a2.w, ds * s2.w));
    o[96] = make_float4(fmaf(dc, a3.x, ds * s3.x), fmaf(dc, a3.y, ds * s3.y),
                        fmaf(dc, a3.z, ds * s3.z), fmaf(dc, a3.w, ds * s3.w));
}

__global__ void k_gather2(const float* __restrict__ b2, float4* __restrict__ out) {
    int c = (blockIdx.x * blockDim.x + threadIdx.x) >> 5;
    int lane = threadIdx.x & 31;
    if (c >= NN) return;
    int s = g_ptr[c], e = g_ptr[c + 1];
    float4 a = make_float4(0, 0, 0, 0);
    for (int j = s; j < e; j++) {
        int r = g_csr_src[j];
        float w = g_wcsr[j];
        float4 v = g_xw2[(size_t)r * 32 + lane];
        a.x = fmaf(w, v.x, a.x); a.y = fmaf(w, v.y, a.y);
        a.z = fmaf(w, v.z, a.z); a.w = fmaf(w, v.w, a.w);
    }
    float dc = g_dinv[c];
    float ds = dc * dc;
    float4 sv = g_xw2[(size_t)c * 32 + lane];
    float4 bb = ((const float4*)b2)[lane];
    out[(size_t)c * 32 + lane] = make_float4(
        fmaf(dc, a.x, fmaf(ds, sv.x, bb.x)), fmaf(dc, a.y, fmaf(ds, sv.y, bb.y)),
        fmaf(dc, a.z, fmaf(ds, sv.z, bb.z)), fmaf(dc, a.w, fmaf(ds, sv.w, bb.w)));
}

// ---------------- relu(agg1+b1) -> out1 (g_xw1) + similarity dots -----------
__global__ void k_relu_sim(const float* __restrict__ b1, const float* __restrict__ Wm) {
    int i = blockIdx.x;
    int t = threadIdx.x;
    size_t base = (size_t)i * (D1 / 4);
    float4 v = g_agg1[base + t];
    float4 bb = ((const float4*)b1)[t];
    float4 r;
    r.x = fmaxf(v.x + bb.x, 0.0f);
    r.y = fmaxf(v.y + bb.y, 0.0f);
    r.z = fmaxf(v.z + bb.z, 0.0f);
    r.w = fmaxf(v.w + bb.w, 0.0f);
    g_xw1[base + t] = r;

    float4 ws = ((const float4*)Wm)[t];
    float4 wd = ((const float4*)Wm)[t + 128];
    float ps = r.x * ws.x + r.y * ws.y + r.z * ws.z + r.w * ws.w;
    float pd = r.x * wd.x + r.y * wd.y + r.z * wd.z + r.w * wd.w;
    #pragma unroll
    for (int o = 16; o > 0; o >>= 1) {
        ps += __shfl_down_sync(0xffffffffu, ps, o);
        pd += __shfl_down_sync(0xffffffffu, pd, o);
    }
    __shared__ float sps[4], spd[4];
    if ((t & 31) == 0) { sps[t >> 5] = ps; spd[t >> 5] = pd; }
    __syncthreads();
    if (t == 0) {
        g_ssrc[i] = sps[0] + sps[1] + sps[2] + sps[3];
        g_sdst[i] = spd[0] + spd[1] + spd[2] + spd[3];
    }
}

// ---------------- mma.sync bf16-split GEMM (wide-N, cp.async B) -------------
// MODE 0: C[NN,512] = node_attr @ W1 ; BM=128, BN=256, 512 thr (warps 2x8), grid.y=2
// MODE 1: C[NN,128] = out1 @ W2      ; BM=128, BN=128, 256 thr (warps 2x4), grid.y=1
#define GBK 32
#define LDA 40    // bf16 units, 80B stride, conflict-free ldmatrix

__device__ __forceinline__ void ldsm_x4(uint32_t* r, const __nv_bfloat16* p) {
    uint32_t a = (uint32_t)__cvta_generic_to_shared(p);
    asm volatile("ldmatrix.sync.aligned.m8n8.x4.shared.b16 {%0,%1,%2,%3}, [%4];"
                 : "=r"(r[0]), "=r"(r[1]), "=r"(r[2]), "=r"(r[3]) : "r"(a));
}
__device__ __forceinline__ void ldsm_x2t(uint32_t* r, const __nv_bfloat16* p) {
    uint32_t a = (uint32_t)__cvta_generic_to_shared(p);
    asm volatile("ldmatrix.sync.aligned.m8n8.x2.trans.shared.b16 {%0,%1}, [%2];"
                 : "=r"(r[0]), "=r"(r[1]) : "r"(a));
}
__device__ __forceinline__ void mma_bf16(float* c, const uint32_t* a, const uint32_t* b) {
    asm volatile(
        "mma.sync.aligned.m16n8k16.row.col.f32.bf16.bf16.f32 "
        "{%0,%1,%2,%3},{%4,%5,%6,%7},{%8,%9},{%0,%1,%2,%3};"
        : "+f"(c[0]), "+f"(c[1]), "+f"(c[2]), "+f"(c[3])
        : "r"(a[0]), "r"(a[1]), "r"(a[2]), "r"(a[3]), "r"(b[0]), "r"(b[1]));
}
__device__ __forceinline__ void cp16(const __nv_bfloat16* dst, const void* src) {
    uint32_t d = (uint32_t)__cvta_generic_to_shared(dst);
    asm volatile("cp.async.cg.shared.global [%0], [%1], 16;" :: "r"(d), "l"(src));
}

template <int MODE>
__global__ void __launch_bounds__((MODE == 0) ? 512 : 256, 1)
mma_gemm(const float* __restrict__ Aarg) {
    constexpr int K = (MODE == 0) ? K1 : D1;
    constexpr int BN = (MODE == 0) ? 256 : 128;
    constexpr int NG = (MODE == 0) ? D1 : D2;
    constexpr int THREADS = (MODE == 0) ? 512 : 256;
    constexpr int NWN = BN / 32;               // warps along N (8 or 4)
    constexpr int LDB = BN + 8;
    constexpr int NAIT = 512 / THREADS;        // A float4-pair iters (1 or 2)
    constexpr int NBIT = 2;                    // B uint4 iters per buffer... (32*BN/8)/THREADS
    constexpr int ASZ = 128 * LDA;             // bf16 elems

    extern __shared__ __nv_bfloat16 smem[];
    __nv_bfloat16* sAh = smem;
    __nv_bfloat16* sAl = sAh + ASZ;
    __nv_bfloat16* sBh = sAl + ASZ;
    __nv_bfloat16* sBl = sBh + GBK * LDB;

    const float* __restrict__ A = (MODE == 0) ? Aarg : (const float*)g_xw1;
    const __nv_bfloat16* __restrict__ BhG = (MODE == 0) ? g_w1h : g_w2h;
    const __nv_bfloat16* __restrict__ BlG = (MODE == 0) ? g_w1l : g_w2l;
    float* __restrict__ C = (MODE == 0) ? (float*)g_xw1 : (float*)g_xw2;

    const int tid = threadIdx.x;
    const int lane = tid & 31;
    const int wid = tid >> 5;
    const int warp_m = wid / NWN;              // 0..1 (64 rows each)
    const int warp_n = wid % NWN;              // 32 cols each
    const int bm0 = blockIdx.x * 128;
    const int bn0 = blockIdx.y * BN;

    float acc[4][4][4];
    #pragma unroll
    for (int i = 0; i < 4; i++)
        #pragma unroll
        for (int j = 0; j < 4; j++)
            #pragma unroll
            for (int q = 0; q < 4; q++) acc[i][j][q] = 0.0f;

    float4 ra[2 * NAIT];
    const float4 zf4 = make_float4(0, 0, 0, 0);

    // prefetch A chunk 0
    #pragma unroll
    for (int i = 0; i < NAIT; i++) {
        int idx = tid + i * THREADS;           // over 128 rows x 4 col-groups
        int row = idx >> 2, cg = (idx & 3) * 8;
        size_t ar = (size_t)min(bm0 + row, NN - 1);
        ra[2 * i]     = *(const float4*)(A + ar * K + cg);
        ra[2 * i + 1] = *(const float4*)(A + ar * K + cg + 4);
    }

    #pragma unroll 1
    for (int k0 = 0; k0 < K; k0 += GBK) {
        __syncthreads();   // consumers done with smem

        // store A (split fp32 -> bf16 hi/lo)
        #pragma unroll
        for (int i = 0; i < NAIT; i++) {
            int idx = tid + i * THREADS;
            int row = idx >> 2, cg = (idx & 3) * 8;
            uint2 h0, l0, h1, l1;
            split4(ra[2 * i], h0, l0);
            split4(ra[2 * i + 1], h1, l1);
            *(uint4*)&sAh[row * LDA + cg] = make_uint4(h0.x, h0.y, h1.x, h1.y);
            *(uint4*)&sAl[row * LDA + cg] = make_uint4(l0.x, l0.y, l1.x, l1.y);
        }
        // cp.async B chunk (32 k-rows x BN cols, hi+lo)
        #pragma unroll
        for (int i = 0; i < NBIT; i++) {
            int idx = tid + i * THREADS;       // over 32*(BN/8) uint4 slots
            int row = idx / (BN / 8), colg = (idx % (BN / 8)) * 8;
            size_t off = (size_t)(k0 + row) * NG + bn0 + colg;
            cp16(&sBh[row * LDB + colg], BhG + off);
            cp16(&sBl[row * LDB + colg], BlG + off);
        }
        asm volatile("cp.async.commit_group;" ::: "memory");

        // prefetch next A chunk
        const int kn = k0 + GBK;
        if (kn < K) {
            #pragma unroll
            for (int i = 0; i < NAIT; i++) {
                int idx = tid + i * THREADS;
                int row = idx >> 2, cg = (idx & 3) * 8;
                size_t ar = (size_t)min(bm0 + row, NN - 1);
                ra[2 * i]     = *(const float4*)(A + ar * K + kn + cg);
                ra[2 * i + 1] = *(const float4*)(A + ar * K + kn + cg + 4);
            }
        }

        asm volatile("cp.async.wait_group 0;" ::: "memory");
        __syncthreads();

        #pragma unroll
        for (int kk = 0; kk < GBK; kk += 16) {
            uint32_t bh[4][2], bl[4][2];
            #pragma unroll
            for (int nt = 0; nt < 4; nt++) {
                const int krow = kk + (lane & 15);
                const int noff = warp_n * 32 + nt * 8;
                ldsm_x2t(bh[nt], &sBh[krow * LDB + noff]);
                ldsm_x2t(bl[nt], &sBl[krow * LDB + noff]);
            }
            #pragma unroll
            for (int mt = 0; mt < 4; mt++) {
                uint32_t ah[4], al[4];
                const int mrow = warp_m * 64 + mt * 16 + (lane & 15);
                const int koff = kk + ((lane >> 4) << 3);
                ldsm_x4(ah, &sAh[mrow * LDA + koff]);
                ldsm_x4(al, &sAl[mrow * LDA + koff]);
                #pragma unroll
                for (int nt = 0; nt < 4; nt++) {
                    mma_bf16(acc[mt][nt], ah, bh[nt]);
                    mma_bf16(acc[mt][nt], ah, bl[nt]);
                    mma_bf16(acc[mt][nt], al, bh[nt]);
                }
            }
        }
    }

    // epilogue
    #pragma unroll
    for (int mt = 0; mt < 4; mt++) {
        const int r0 = bm0 + warp_m * 64 + mt * 16 + (lane >> 2);
        const int r1 = r0 + 8;
        #pragma unroll
        for (int nt = 0; nt < 4; nt++) {
            const int cc = bn0 + warp_n * 32 + nt * 8 + (lane & 3) * 2;
            if (r0 < NN)
                *(float2*)&C[(size_t)r0 * NG + cc] = make_float2(acc[mt][nt][0], acc[mt][nt][1]);
            if (r1 < NN)
                *(float2*)&C[(size_t)r1 * NG + cc] = make_float2(acc[mt][nt][2], acc[mt][nt][3]);
        }
    }
}

// ---------------- launch ----------------------------------------------------
extern "C" void kernel_launch(void* const* d_in, const int* in_sizes, int n_in,
                              void* d_out, int out_size) {
    const float* node_attr = (const float*)d_in[0];
    const float* edge_attr = (const float*)d_in[1];
    const void*  edge_index = d_in[2];
    const float* W1 = (const float*)d_in[5];
    const float* b1 = (const float*)d_in[6];
    const float* W2 = (const float*)d_in[7];
    const float* b2 = (const float*)d_in[8];
    const float* Wm = (const float*)d_in[9];
    const float* bm = (const float*)d_in[10];
    float4* out = (float4*)d_out;

    const int nodeBlocks = (NN + 255) / 256;
    const int edgeBlocks = (NE + 255) / 256;
    const int warpNodeBlocks = (NN * 32 + 255) / 256;
    const int mTiles = (NN + 127) / 128;

    // dynamic smem: A 2*128*40*2 = 20480 ; B 2*32*(BN+8)*2
    const int smem0 = 20480 + 2 * 32 * (256 + 8) * 2;   // 54272
    const int smem1 = 20480 + 2 * 32 * (128 + 8) * 2;   // 37888
    cudaFuncSetAttribute(mma_gemm<0>, cudaFuncAttributeMaxDynamicSharedMemorySize, smem0);
    cudaFuncSetAttribute(mma_gemm<1>, cudaFuncAttributeMaxDynamicSharedMemorySize, smem1);

    // ---- edge_index convert + CSR build
    k_detect<<<1, 32>>>((const int*)edge_index);
    k_zero_cnt<<<nodeBlocks, 256>>>();
    k_convert<<<edgeBlocks, 256>>>(edge_index);
    k_scan_block<<<NB_SCAN, 256>>>();
    k_scan_bsum<<<1, 32>>>();
    k_scan_add<<<nodeBlocks, 256>>>();
    k_fill<<<edgeBlocks, 256>>>();

    // ---- weight splits (small)
    k_split<1><<<((K1 * D1 / 4) + 255) / 256, 256>>>((const float4*)W1, K1 * D1 / 4);
    k_split<2><<<((D1 * D2 / 4) + 255) / 256, 256>>>((const float4*)W2, D1 * D2 / 4);

    // ---- layer 1: deg/dinv + per-slot weights
    k_deg1<<<nodeBlocks, 256>>>(edge_attr);
    k_w1pre<<<edgeBlocks, 256>>>(edge_attr);

    // ---- layer 1: xw1 = node_attr @ W1
    mma_gemm<0><<<dim3(mTiles, 2), 512, smem0>>>(node_attr);

    // ---- layer 1: CSR gather (edges + self)
    k_gather1<<<warpNodeBlocks, 256>>>();

    // ---- relu + bias -> out1 ; similarity dots
    k_relu_sim<<<NN, 128>>>(b1, Wm);

    // ---- layer 2: e2 + deg/dinv + weights
    k_deg2<<<nodeBlocks, 256>>>(bm);
    k_w2pre<<<edgeBlocks, 256>>>();

    // ---- layer 2: xw2 = out1 @ W2
    mma_gemm<1><<<dim3(mTiles, 1), 256, smem1>>>(nullptr);

    // ---- layer 2: CSR gather into output (+ bias, self)
    k_gather2<<<warpNodeBlocks, 256>>>(b2, out);

    (void)in_sizes; (void)n_in; (void)out_size;
}

// round 13
// speedup vs baseline: 1.2234x; 1.2234x over previous
#include <cuda_runtime.h>
#include <cuda_fp16.h>
#include <cstddef>
#include <cstdint>

#define NN 100000
#define NE 1600000
#define D1 512      // hidden dim (layer1 out)
#define D2 128      // output dim
#define K1 1024     // input dim
#define NB_SCAN ((NN + 255) / 256)

// ---------------- scratch (static device globals; referenced ONLY from device code) ---
__device__ float4 g_xw1[(size_t)NN * D1 / 4];   // x @ W1 (pre-activation)
__device__ float4 g_agg1[(size_t)NN * D1 / 4];  // out1 = relu(agg + b1)
__device__ float4 g_xw2[(size_t)NN * D2 / 4];   // out1 @ W2
__device__ float  g_dinv[NN];
__device__ float  g_ssrc[NN];
__device__ float  g_sdst[NN];
__device__ int    g_row[NE];
__device__ int    g_col[NE];
__device__ int    g_is64;

// CSR (grouped by destination col)
__device__ int    g_cnt[NN];
__device__ int    g_ptr[NN + 1];
__device__ int    g_cur[NN];
__device__ int    g_bsum[NB_SCAN];
__device__ int    g_boff[NB_SCAN];
__device__ int    g_csr_src[NE];
__device__ int    g_csr_eid[NE];
__device__ float  g_wcsr[NE];
__device__ float  g_e2[NE];

// fp16 weights (single precision level; B rounding error ~2^-12 is the only loss)
__device__ __half g_w1h[(size_t)K1 * D1];
__device__ __half g_w2h[(size_t)D1 * D2];

// ---------------- helpers ---------------------------------------------------
// split fp32x4 -> fp16 hi (ph) + fp16 lo (pl); hi+lo represents A to ~2^-24
__device__ __forceinline__ void split4h(float4 v, uint2& ph, uint2& pl) {
    __half h0 = __float2half_rn(v.x);
    __half h1 = __float2half_rn(v.y);
    __half h2 = __float2half_rn(v.z);
    __half h3 = __float2half_rn(v.w);
    __half l0 = __float2half_rn(v.x - __half2float(h0));
    __half l1 = __float2half_rn(v.y - __half2float(h1));
    __half l2 = __float2half_rn(v.z - __half2float(h2));
    __half l3 = __float2half_rn(v.w - __half2float(h3));
    ph.x = ((uint32_t)__half_as_ushort(h1) << 16) | __half_as_ushort(h0);
    ph.y = ((uint32_t)__half_as_ushort(h3) << 16) | __half_as_ushort(h2);
    pl.x = ((uint32_t)__half_as_ushort(l1) << 16) | __half_as_ushort(l0);
    pl.y = ((uint32_t)__half_as_ushort(l3) << 16) | __half_as_ushort(l2);
}

// WHICH 1: W1 -> g_w1h ; 2: W2 -> g_w2h   (fp32 -> fp16, single)
template <int WHICH>
__global__ void k_split(const float4* __restrict__ src, int n4) {
    int idx = blockIdx.x * blockDim.x + threadIdx.x;
    if (idx >= n4) return;
    __half* Dh = (WHICH == 1) ? g_w1h : g_w2h;
    float4 v = src[idx];
    uint2 p;
    p.x = ((uint32_t)__half_as_ushort(__float2half_rn(v.y)) << 16) |
          __half_as_ushort(__float2half_rn(v.x));
    p.y = ((uint32_t)__half_as_ushort(__float2half_rn(v.w)) << 16) |
          __half_as_ushort(__float2half_rn(v.z));
    ((uint2*)Dh)[idx] = p;
}

// ---------------- edge_index dtype detect + convert + histogram ------------
__global__ void k_detect(const int* __restrict__ ei32) {
    if (blockIdx.x != 0 || threadIdx.x != 0) return;
    int is64 = 1;
    for (int i = 1; i < 512; i += 2) {
        if (ei32[i] != 0) { is64 = 0; break; }
    }
    g_is64 = is64;
}

__global__ void k_zero_cnt() {
    int i = blockIdx.x * blockDim.x + threadIdx.x;
    if (i < NN) g_cnt[i] = 0;
}

__global__ void k_convert(const void* __restrict__ ei) {
    int e = blockIdx.x * blockDim.x + threadIdx.x;
    if (e >= NE) return;
    int r, c;
    if (g_is64) {
        const long long* p = (const long long*)ei;
        r = (int)p[e];
        c = (int)p[NE + e];
    } else {
        const int* p = (const int*)ei;
        r = p[e];
        c = p[NE + e];
    }
    g_row[e] = r;
    g_col[e] = c;
    atomicAdd(&g_cnt[c], 1);
}

// ---------------- exclusive scan of g_cnt -> g_ptr --------------------------
__global__ void k_scan_block() {
    __shared__ int sh[256];
    int i = blockIdx.x * 256 + threadIdx.x;
    int v = (i < NN) ? g_cnt[i] : 0;
    sh[threadIdx.x] = v;
    __syncthreads();
    #pragma unroll
    for (int o = 1; o < 256; o <<= 1) {
        int t = (threadIdx.x >= o) ? sh[threadIdx.x - o] : 0;
        __syncthreads();
        sh[threadIdx.x] += t;
        __syncthreads();
    }
    if (i < NN) g_ptr[i] = sh[threadIdx.x] - v;
    if (threadIdx.x == 255) g_bsum[blockIdx.x] = sh[255];
}

__global__ void k_scan_bsum() {
    if (blockIdx.x != 0 || threadIdx.x != 0) return;
    int run = 0;
    for (int b = 0; b < NB_SCAN; b++) {
        g_boff[b] = run;
        run += g_bsum[b];
    }
}

__global__ void k_scan_add() {
    int i = blockIdx.x * blockDim.x + threadIdx.x;
    if (i < NN) {
        int p = g_ptr[i] + g_boff[i >> 8];
        g_ptr[i] = p;
        g_cur[i] = p;
    }
    if (i == 0) g_ptr[NN] = NE;
}

__global__ void k_fill() {
    int e = blockIdx.x * blockDim.x + threadIdx.x;
    if (e >= NE) return;
    int c = g_col[e];
    int pos = atomicAdd(&g_cur[c], 1);
    g_csr_src[pos] = g_row[e];
    g_csr_eid[pos] = e;
}

// ---------------- per-node degree / dinv (atomic-free via CSR) --------------
__global__ void k_deg1(const float* __restrict__ ew) {
    int i = blockIdx.x * blockDim.x + threadIdx.x;
    if (i >= NN) return;
    int s = g_ptr[i], e = g_ptr[i + 1];
    float acc = 0.0f;
    for (int j = s; j < e; j++) acc += ew[g_csr_eid[j]];
    g_dinv[i] = rsqrtf(1.0f + acc);
}

__global__ void k_deg2(const float* __restrict__ bm) {
    int i = blockIdx.x * blockDim.x + threadIdx.x;
    if (i >= NN) return;
    int s = g_ptr[i], e = g_ptr[i + 1];
    float sd = g_sdst[i] + bm[0];
    float acc = 0.0f;
    for (int j = s; j < e; j++) {
        float v = fmaxf(g_ssrc[g_csr_src[j]] + sd, 0.0f);
        g_e2[j] = v;
        acc += v;
    }
    g_dinv[i] = rsqrtf(1.0f + acc);
}

__global__ void k_w1pre(const float* __restrict__ ew) {
    int j = blockIdx.x * blockDim.x + threadIdx.x;
    if (j < NE) g_wcsr[j] = g_dinv[g_csr_src[j]] * ew[g_csr_eid[j]];
}
__global__ void k_w2pre() {
    int j = blockIdx.x * blockDim.x + threadIdx.x;
    if (j < NE) g_wcsr[j] = g_dinv[g_csr_src[j]] * g_e2[j];
}

// ---------------- CSR gather aggregation (no atomics) -----------------------
// layer1 FUSED: aggregate + self + bias + relu -> out1 (g_agg1), plus
// similarity dots ssrc/sdst (warp reduction). One warp per dst node.
__global__ void k_gather1(const float* __restrict__ b1, const float* __restrict__ Wm) {
    int c = (blockIdx.x * blockDim.x + threadIdx.x) >> 5;
    int lane = threadIdx.x & 31;
    if (c >= NN) return;
    int s = g_ptr[c], e = g_ptr[c + 1];
    float4 a0 = make_float4(0, 0, 0, 0), a1 = a0, a2 = a0, a3 = a0;
    for (int j = s; j < e; j++) {
        int r = g_csr_src[j];
        float w = g_wcsr[j];
        const float4* x = g_xw1 + (size_t)r * 128 + lane;
        float4 v0 = x[0], v1 = x[32], v2 = x[64], v3 = x[96];
        a0.x = fmaf(w, v0.x, a0.x); a0.y = fmaf(w, v0.y, a0.y);
        a0.z = fmaf(w, v0.z, a0.z); a0.w = fmaf(w, v0.w, a0.w);
        a1.x = fmaf(w, v1.x, a1.x); a1.y = fmaf(w, v1.y, a1.y);
        a1.z = fmaf(w, v1.z, a1.z); a1.w = fmaf(w, v1.w, a1.w);
        a2.x = fmaf(w, v2.x, a2.x); a2.y = fmaf(w, v2.y, a2.y);
        a2.z = fmaf(w, v2.z, a2.z); a2.w = fmaf(w, v2.w, a2.w);
        a3.x = fmaf(w, v3.x, a3.x); a3.y = fmaf(w, v3.y, a3.y);
        a3.z = fmaf(w, v3.z, a3.z); a3.w = fmaf(w, v3.w, a3.w);
    }
    float dc = g_dinv[c];
    float ds = dc * dc;
    const float4* xc = g_xw1 + (size_t)c * 128 + lane;
    float4 s0 = xc[0], s1 = xc[32], s2 = xc[64], s3 = xc[96];
    const float4* B1 = (const float4*)b1;
    float4 b0 = B1[lane], bb1 = B1[lane + 32], bb2 = B1[lane + 64], bb3 = B1[lane + 96];

    float4 o0, o1, o2, o3;
    o0.x = fmaxf(fmaf(dc, a0.x, fmaf(ds, s0.x, b0.x)), 0.0f);
    o0.y = fmaxf(fmaf(dc, a0.y, fmaf(ds, s0.y, b0.y)), 0.0f);
    o0.z = fmaxf(fmaf(dc, a0.z, fmaf(ds, s0.z, b0.z)), 0.0f);
    o0.w = fmaxf(fmaf(dc, a0.w, fmaf(ds, s0.w, b0.w)), 0.0f);
    o1.x = fmaxf(fmaf(dc, a1.x, fmaf(ds, s1.x, bb1.x)), 0.0f);
    o1.y = fmaxf(fmaf(dc, a1.y, fmaf(ds, s1.y, bb1.y)), 0.0f);
    o1.z = fmaxf(fmaf(dc, a1.z, fmaf(ds, s1.z, bb1.z)), 0.0f);
    o1.w = fmaxf(fmaf(dc, a1.w, fmaf(ds, s1.w, bb1.w)), 0.0f);
    o2.x = fmaxf(fmaf(dc, a2.x, fmaf(ds, s2.x, bb2.x)), 0.0f);
    o2.y = fmaxf(fmaf(dc, a2.y, fmaf(ds, s2.y, bb2.y)), 0.0f);
    o2.z = fmaxf(fmaf(dc, a2.z, fmaf(ds, s2.z, bb2.z)), 0.0f);
    o2.w = fmaxf(fmaf(dc, a2.w, fmaf(ds, s2.w, bb2.w)), 0.0f);
    o3.x = fmaxf(fmaf(dc, a3.x, fmaf(ds, s3.x, bb3.x)), 0.0f);
    o3.y = fmaxf(fmaf(dc, a3.y, fmaf(ds, s3.y, bb3.y)), 0.0f);
    o3.z = fmaxf(fmaf(dc, a3.z, fmaf(ds, s3.z, bb3.z)), 0.0f);
    o3.w = fmaxf(fmaf(dc, a3.w, fmaf(ds, s3.w, bb3.w)), 0.0f);

    float4* o = g_agg1 + (size_t)c * 128 + lane;
    o[0] = o0; o[32] = o1; o[64] = o2; o[96] = o3;

    // similarity dots
    const float4* WM = (const float4*)Wm;
    float4 w0 = WM[lane], w1 = WM[lane + 32], w2 = WM[lane + 64], w3 = WM[lane + 96];
    float ps = o0.x * w0.x + o0.y * w0.y + o0.z * w0.z + o0.w * w0.w
             + o1.x * w1.x + o1.y * w1.y + o1.z * w1.z + o1.w * w1.w
             + o2.x * w2.x + o2.y * w2.y + o2.z * w2.z + o2.w * w2.w
             + o3.x * w3.x + o3.y * w3.y + o3.z * w3.z + o3.w * w3.w;
    w0 = WM[lane + 128]; w1 = WM[lane + 160]; w2 = WM[lane + 192]; w3 = WM[lane + 224];
    float pd = o0.x * w0.x + o0.y * w0.y + o0.z * w0.z + o0.w * w0.w
             + o1.x * w1.x + o1.y * w1.y + o1.z * w1.z + o1.w * w1.w
             + o2.x * w2.x + o2.y * w2.y + o2.z * w2.z + o2.w * w2.w
             + o3.x * w3.x + o3.y * w3.y + o3.z * w3.z + o3.w * w3.w;
    #pragma unroll
    for (int off = 16; off > 0; off >>= 1) {
        ps += __shfl_down_sync(0xffffffffu, ps, off);
        pd += __shfl_down_sync(0xffffffffu, pd, off);
    }
    if (lane == 0) {
        g_ssrc[c] = ps;
        g_sdst[c] = pd;
    }
}

__global__ void k_gather2(const float* __restrict__ b2, float4* __restrict__ out) {
    int c = (blockIdx.x * blockDim.x + threadIdx.x) >> 5;
    int lane = threadIdx.x & 31;
    if (c >= NN) return;
    int s = g_ptr[c], e = g_ptr[c + 1];
    float4 a = make_float4(0, 0, 0, 0);
    for (int j = s; j < e; j++) {
        int r = g_csr_src[j];
        float w = g_wcsr[j];
        float4 v = g_xw2[(size_t)r * 32 + lane];
        a.x = fmaf(w, v.x, a.x); a.y = fmaf(w, v.y, a.y);
        a.z = fmaf(w, v.z, a.z); a.w = fmaf(w, v.w, a.w);
    }
    float dc = g_dinv[c];
    float ds = dc * dc;
    float4 sv = g_xw2[(size_t)c * 32 + lane];
    float4 bb = ((const float4*)b2)[lane];
    out[(size_t)c * 32 + lane] = make_float4(
        fmaf(dc, a.x, fmaf(ds, sv.x, bb.x)), fmaf(dc, a.y, fmaf(ds, sv.y, bb.y)),
        fmaf(dc, a.z, fmaf(ds, sv.z, bb.z)), fmaf(dc, a.w, fmaf(ds, sv.w, bb.w)));
}

// ---------------- mma.sync fp16 2-term GEMM (R8 structure) ------------------
// C(fp32) = Ah*B + Al*B, A = Ah+Al exact in fp16 pair, B = fp16 (2^-12 rounding)
// MODE 0: A = node_attr [NN,1024], B = g_w1h [1024,512], C = g_xw1
// MODE 1: A = g_agg1(out1) [NN,512], B = g_w2h [512,128], C = g_xw2
#define GBM 128
#define GBN 128
#define GBK 32
#define LDA 40    // halves, 80B stride -> conflict-free ldmatrix
#define LDB 136   // halves, 272B stride -> conflict-free ldmatrix

__device__ __forceinline__ void ldsm_x4(uint32_t* r, const __half* p) {
    uint32_t a = (uint32_t)__cvta_generic_to_shared(p);
    asm volatile("ldmatrix.sync.aligned.m8n8.x4.shared.b16 {%0,%1,%2,%3}, [%4];"
                 : "=r"(r[0]), "=r"(r[1]), "=r"(r[2]), "=r"(r[3]) : "r"(a));
}
__device__ __forceinline__ void ldsm_x2t(uint32_t* r, const __half* p) {
    uint32_t a = (uint32_t)__cvta_generic_to_shared(p);
    asm volatile("ldmatrix.sync.aligned.m8n8.x2.trans.shared.b16 {%0,%1}, [%2];"
                 : "=r"(r[0]), "=r"(r[1]) : "r"(a));
}
__device__ __forceinline__ void mma_fp16(float* c, const uint32_t* a, const uint32_t* b) {
    asm volatile(
        "mma.sync.aligned.m16n8k16.row.col.f32.f16.f16.f32 "
        "{%0,%1,%2,%3},{%4,%5,%6,%7},{%8,%9},{%0,%1,%2,%3};"
        : "+f"(c[0]), "+f"(c[1]), "+f"(c[2]), "+f"(c[3])
        : "r"(a[0]), "r"(a[1]), "r"(a[2]), "r"(a[3]), "r"(b[0]), "r"(b[1]));
}

template <int MODE>
__global__ void __launch_bounds__(256, 1) mma_gemm(const float* __restrict__ Aarg) {
    constexpr int K = (MODE == 0) ? K1 : D1;
    constexpr int N = (MODE == 0) ? D1 : D2;
    const float* __restrict__ A = (MODE == 0) ? Aarg : (const float*)g_agg1;
    const __half* __restrict__ BhG = (MODE == 0) ? g_w1h : g_w2h;
    float* __restrict__ C = (MODE == 0) ? (float*)g_xw1 : (float*)g_xw2;

    __shared__ __half sAh[GBM * LDA];
    __shared__ __half sAl[GBM * LDA];
    __shared__ __half sBh[GBK * LDB];

    const int tid = threadIdx.x;
    const int lane = tid & 31;
    const int wid = tid >> 5;
    const int warp_m = wid >> 2;           // 0..1 (64 rows each)
    const int warp_n = wid & 3;            // 0..3 (32 cols each)
    const int bm0 = blockIdx.y * GBM;
    const int bn0 = blockIdx.x * GBN;

    const int arow = tid >> 2;             // 0..63 (two halves)
    const int acol = (tid & 3) * 8;        // 0,8,16,24
    const int brow = tid >> 4;             // 0..15 (two halves)
    const int bcol = (tid & 15) * 8;       // 0..120

    const bool av0 = (bm0 + arow) < NN;
    const bool av1 = (bm0 + 64 + arow) < NN;
    const size_t ar0 = (size_t)min(bm0 + arow, NN - 1);
    const size_t ar1 = (size_t)min(bm0 + 64 + arow, NN - 1);

    float acc[4][4][4];
    #pragma unroll
    for (int i = 0; i < 4; i++)
        #pragma unroll
        for (int j = 0; j < 4; j++)
            #pragma unroll
            for (int q = 0; q < 4; q++) acc[i][j][q] = 0.0f;

    float4 ra[4];
    uint4 rb[2];
    const float4 zf4 = make_float4(0, 0, 0, 0);

    // prefetch k0 = 0
    {
        ra[0] = av0 ? *(const float4*)(A + ar0 * K + acol) : zf4;
        ra[1] = av0 ? *(const float4*)(A + ar0 * K + acol + 4) : zf4;
        ra[2] = av1 ? *(const float4*)(A + ar1 * K + acol) : zf4;
        ra[3] = av1 ? *(const float4*)(A + ar1 * K + acol + 4) : zf4;
        rb[0] = *(const uint4*)(BhG + (size_t)brow * N + bn0 + bcol);
        rb[1] = *(const uint4*)(BhG + (size_t)(16 + brow) * N + bn0 + bcol);
    }

    #pragma unroll 1
    for (int k0 = 0; k0 < K; k0 += GBK) {
        __syncthreads();
        {
            uint2 h0, l0, h1, l1;
            split4h(ra[0], h0, l0);
            split4h(ra[1], h1, l1);
            *(uint4*)&sAh[arow * LDA + acol] = make_uint4(h0.x, h0.y, h1.x, h1.y);
            *(uint4*)&sAl[arow * LDA + acol] = make_uint4(l0.x, l0.y, l1.x, l1.y);
            split4h(ra[2], h0, l0);
            split4h(ra[3], h1, l1);
            *(uint4*)&sAh[(arow + 64) * LDA + acol] = make_uint4(h0.x, h0.y, h1.x, h1.y);
            *(uint4*)&sAl[(arow + 64) * LDA + acol] = make_uint4(l0.x, l0.y, l1.x, l1.y);
        }
        *(uint4*)&sBh[brow * LDB + bcol] = rb[0];
        *(uint4*)&sBh[(brow + 16) * LDB + bcol] = rb[1];
        __syncthreads();

        const int kn = k0 + GBK;
        if (kn < K) {
            ra[0] = av0 ? *(const float4*)(A + ar0 * K + kn + acol) : zf4;
            ra[1] = av0 ? *(const float4*)(A + ar0 * K + kn + acol + 4) : zf4;
            ra[2] = av1 ? *(const float4*)(A + ar1 * K + kn + acol) : zf4;
            ra[3] = av1 ? *(const float4*)(A + ar1 * K + kn + acol + 4) : zf4;
            rb[0] = *(const uint4*)(BhG + (size_t)(kn + brow) * N + bn0 + bcol);
            rb[1] = *(const uint4*)(BhG + (size_t)(kn + 16 + brow) * N + bn0 + bcol);
        }

        #pragma unroll
        for (int kk = 0; kk < GBK; kk += 16) {
            uint32_t ah[4][4], al[4][4], bh[4][2];
            #pragma unroll
            for (int mt = 0; mt < 4; mt++) {
                const int mrow = warp_m * 64 + mt * 16 + (lane & 15);
                const int koff = kk + ((lane >> 4) << 3);
                ldsm_x4(ah[mt], &sAh[mrow * LDA + koff]);
                ldsm_x4(al[mt], &sAl[mrow * LDA + koff]);
            }
            #pragma unroll
            for (int nt = 0; nt < 4; nt++) {
                const int krow = kk + (lane & 15);
                const int noff = warp_n * 32 + nt * 8;
                ldsm_x2t(bh[nt], &sBh[krow * LDB + noff]);
            }
            #pragma unroll
            for (int mt = 0; mt < 4; mt++)
                #pragma unroll
                for (int nt = 0; nt < 4; nt++) {
                    mma_fp16(acc[mt][nt], ah[mt], bh[nt]);
                    mma_fp16(acc[mt][nt], al[mt], bh[nt]);
                }
        }
    }

    // epilogue
    #pragma unroll
    for (int mt = 0; mt < 4; mt++) {
        const int r0 = bm0 + warp_m * 64 + mt * 16 + (lane >> 2);
        const int r1 = r0 + 8;
        #pragma unroll
        for (int nt = 0; nt < 4; nt++) {
            const int cc = bn0 + warp_n * 32 + nt * 8 + (lane & 3) * 2;
            if (r0 < NN)
                *(float2*)&C[(size_t)r0 * N + cc] = make_float2(acc[mt][nt][0], acc[mt][nt][1]);
            if (r1 < NN)
                *(float2*)&C[(size_t)r1 * N + cc] = make_float2(acc[mt][nt][2], acc[mt][nt][3]);
        }
    }
}

// ---------------- launch ----------------------------------------------------
extern "C" void kernel_launch(void* const* d_in, const int* in_sizes, int n_in,
                              void* d_out, int out_size) {
    const float* node_attr = (const float*)d_in[0];
    const float* edge_attr = (const float*)d_in[1];
    const void*  edge_index = d_in[2];
    const float* W1 = (const float*)d_in[5];
    const float* b1 = (const float*)d_in[6];
    const float* W2 = (const float*)d_in[7];
    const float* b2 = (const float*)d_in[8];
    const float* Wm = (const float*)d_in[9];
    const float* bm = (const float*)d_in[10];
    float4* out = (float4*)d_out;

    const int nodeBlocks = (NN + 255) / 256;
    const int edgeBlocks = (NE + 255) / 256;
    const int warpNodeBlocks = (NN * 32 + 255) / 256;
    const int mTiles = (NN + 127) / 128;

    // ---- edge_index convert + CSR build
    k_detect<<<1, 32>>>((const int*)edge_index);
    k_zero_cnt<<<nodeBlocks, 256>>>();
    k_convert<<<edgeBlocks, 256>>>(edge_index);
    k_scan_block<<<NB_SCAN, 256>>>();
    k_scan_bsum<<<1, 32>>>();
    k_scan_add<<<nodeBlocks, 256>>>();
    k_fill<<<edgeBlocks, 256>>>();

    // ---- weight conversions (fp32 -> fp16, small)
    k_split<1><<<((K1 * D1 / 4) + 255) / 256, 256>>>((const float4*)W1, K1 * D1 / 4);
    k_split<2><<<((D1 * D2 / 4) + 255) / 256, 256>>>((const float4*)W2, D1 * D2 / 4);

    // ---- layer 1: deg/dinv + per-slot weights
    k_deg1<<<nodeBlocks, 256>>>(edge_attr);
    k_w1pre<<<edgeBlocks, 256>>>(edge_attr);

    // ---- layer 1: xw1 = node_attr @ W1  (fp16 2-term mma)
    {
        dim3 grid(D1 / GBN, mTiles);
        mma_gemm<0><<<grid, 256>>>(node_attr);
    }

    // ---- layer 1: CSR gather + self + bias + relu + similarity (FUSED)
    k_gather1<<<warpNodeBlocks, 256>>>(b1, Wm);

    // ---- layer 2: e2 + deg/dinv + weights
    k_deg2<<<nodeBlocks, 256>>>(bm);
    k_w2pre<<<edgeBlocks, 256>>>();

    // ---- layer 2: xw2 = out1 @ W2  (fp16 2-term mma)
    {
        dim3 grid(D2 / GBN, mTiles);
        mma_gemm<1><<<grid, 256>>>(nullptr);
    }

    // ---- layer 2: CSR gather into output (+ bias, self)
    k_gather2<<<warpNodeBlocks, 256>>>(b2, out);

    (void)in_sizes; (void)n_in; (void)out_size;
}

// round 14
// speedup vs baseline: 1.3056x; 1.0671x over previous
#include <cuda_runtime.h>
#include <cuda_fp16.h>
#include <cstddef>
#include <cstdint>

#define NN 100000
#define NE 1600000
#define D1 512      // hidden dim (layer1 out)
#define D2 128      // output dim
#define K1 1024     // input dim
#define NB_SCAN ((NN + 255) / 256)

// ---------------- scratch (static device globals; referenced ONLY from device code) ---
__device__ float4 g_xw1[(size_t)NN * D1 / 4];   // x @ W1 (pre-activation, fp32)
__device__ float4 g_agg1[(size_t)NN * D1 / 4];  // out1 = relu(agg + b1) (fp32)
__device__ float4 g_xw2[(size_t)NN * D2 / 4];   // out1 @ W2 (fp32)
__device__ __half g_xw1h[(size_t)NN * D1];      // fp16 copy of xw1 (gather payload)
__device__ __half g_xw2h[(size_t)NN * D2];      // fp16 copy of xw2 (gather payload)
__device__ float  g_dinv[NN];
__device__ float  g_ssrc[NN];
__device__ float  g_sdst[NN];
__device__ int    g_row[NE];
__device__ int    g_col[NE];
__device__ int    g_is64;

// CSR (grouped by destination col)
__device__ int    g_cnt[NN];
__device__ int    g_ptr[NN + 1];
__device__ int    g_cur[NN];
__device__ int    g_bsum[NB_SCAN];
__device__ int    g_boff[NB_SCAN];
__device__ int    g_csr_src[NE];
__device__ int    g_csr_eid[NE];
__device__ float  g_wcsr[NE];
__device__ float  g_e2[NE];

// fp16 weights
__device__ __half g_w1h[(size_t)K1 * D1];
__device__ __half g_w2h[(size_t)D1 * D2];

// ---------------- helpers ---------------------------------------------------
__device__ __forceinline__ void split4h(float4 v, uint2& ph, uint2& pl) {
    __half h0 = __float2half_rn(v.x);
    __half h1 = __float2half_rn(v.y);
    __half h2 = __float2half_rn(v.z);
    __half h3 = __float2half_rn(v.w);
    __half l0 = __float2half_rn(v.x - __half2float(h0));
    __half l1 = __float2half_rn(v.y - __half2float(h1));
    __half l2 = __float2half_rn(v.z - __half2float(h2));
    __half l3 = __float2half_rn(v.w - __half2float(h3));
    ph.x = ((uint32_t)__half_as_ushort(h1) << 16) | __half_as_ushort(h0);
    ph.y = ((uint32_t)__half_as_ushort(h3) << 16) | __half_as_ushort(h2);
    pl.x = ((uint32_t)__half_as_ushort(l1) << 16) | __half_as_ushort(l0);
    pl.y = ((uint32_t)__half_as_ushort(l3) << 16) | __half_as_ushort(l2);
}

// fma 8 halves (one uint4) into two float4 accumulators
__device__ __forceinline__ void fma8(float4& A, float4& B, uint4 u, float w) {
    float2 p;
    p = __half22float2(*(__half2*)&u.x); A.x = fmaf(w, p.x, A.x); A.y = fmaf(w, p.y, A.y);
    p = __half22float2(*(__half2*)&u.y); A.z = fmaf(w, p.x, A.z); A.w = fmaf(w, p.y, A.w);
    p = __half22float2(*(__half2*)&u.z); B.x = fmaf(w, p.x, B.x); B.y = fmaf(w, p.y, B.y);
    p = __half22float2(*(__half2*)&u.w); B.z = fmaf(w, p.x, B.z); B.w = fmaf(w, p.y, B.w);
}

// WHICH 1: W1 -> g_w1h ; 2: W2 -> g_w2h   (fp32 -> fp16)
template <int WHICH>
__global__ void k_split(const float4* __restrict__ src, int n4) {
    int idx = blockIdx.x * blockDim.x + threadIdx.x;
    if (idx >= n4) return;
    __half* Dh = (WHICH == 1) ? g_w1h : g_w2h;
    float4 v = src[idx];
    uint2 p;
    p.x = ((uint32_t)__half_as_ushort(__float2half_rn(v.y)) << 16) |
          __half_as_ushort(__float2half_rn(v.x));
    p.y = ((uint32_t)__half_as_ushort(__float2half_rn(v.w)) << 16) |
          __half_as_ushort(__float2half_rn(v.z));
    ((uint2*)Dh)[idx] = p;
}

// ---------------- edge_index dtype detect + convert + histogram ------------
__global__ void k_detect(const int* __restrict__ ei32) {
    if (blockIdx.x != 0 || threadIdx.x != 0) return;
    int is64 = 1;
    for (int i = 1; i < 512; i += 2) {
        if (ei32[i] != 0) { is64 = 0; break; }
    }
    g_is64 = is64;
}

__global__ void k_zero_cnt() {
    int i = blockIdx.x * blockDim.x + threadIdx.x;
    if (i < NN) g_cnt[i] = 0;
}

__global__ void k_convert(const void* __restrict__ ei) {
    int e = blockIdx.x * blockDim.x + threadIdx.x;
    if (e >= NE) return;
    int r, c;
    if (g_is64) {
        const long long* p = (const long long*)ei;
        r = (int)p[e];
        c = (int)p[NE + e];
    } else {
        const int* p = (const int*)ei;
        r = p[e];
        c = p[NE + e];
    }
    g_row[e] = r;
    g_col[e] = c;
    atomicAdd(&g_cnt[c], 1);
}

// ---------------- exclusive scan of g_cnt -> g_ptr --------------------------
__global__ void k_scan_block() {
    __shared__ int sh[256];
    int i = blockIdx.x * 256 + threadIdx.x;
    int v = (i < NN) ? g_cnt[i] : 0;
    sh[threadIdx.x] = v;
    __syncthreads();
    #pragma unroll
    for (int o = 1; o < 256; o <<= 1) {
        int t = (threadIdx.x >= o) ? sh[threadIdx.x - o] : 0;
        __syncthreads();
        sh[threadIdx.x] += t;
        __syncthreads();
    }
    if (i < NN) g_ptr[i] = sh[threadIdx.x] - v;
    if (threadIdx.x == 255) g_bsum[blockIdx.x] = sh[255];
}

__global__ void k_scan_bsum() {
    if (blockIdx.x != 0 || threadIdx.x != 0) return;
    int run = 0;
    for (int b = 0; b < NB_SCAN; b++) {
        g_boff[b] = run;
        run += g_bsum[b];
    }
}

__global__ void k_scan_add() {
    int i = blockIdx.x * blockDim.x + threadIdx.x;
    if (i < NN) {
        int p = g_ptr[i] + g_boff[i >> 8];
        g_ptr[i] = p;
        g_cur[i] = p;
    }
    if (i == 0) g_ptr[NN] = NE;
}

__global__ void k_fill() {
    int e = blockIdx.x * blockDim.x + threadIdx.x;
    if (e >= NE) return;
    int c = g_col[e];
    int pos = atomicAdd(&g_cur[c], 1);
    g_csr_src[pos] = g_row[e];
    g_csr_eid[pos] = e;
}

// ---------------- per-node degree / dinv (atomic-free via CSR) --------------
__global__ void k_deg1(const float* __restrict__ ew) {
    int i = blockIdx.x * blockDim.x + threadIdx.x;
    if (i >= NN) return;
    int s = g_ptr[i], e = g_ptr[i + 1];
    float acc = 0.0f;
    for (int j = s; j < e; j++) acc += ew[g_csr_eid[j]];
    g_dinv[i] = rsqrtf(1.0f + acc);
}

__global__ void k_deg2(const float* __restrict__ bm) {
    int i = blockIdx.x * blockDim.x + threadIdx.x;
    if (i >= NN) return;
    int s = g_ptr[i], e = g_ptr[i + 1];
    float sd = g_sdst[i] + bm[0];
    float acc = 0.0f;
    for (int j = s; j < e; j++) {
        float v = fmaxf(g_ssrc[g_csr_src[j]] + sd, 0.0f);
        g_e2[j] = v;
        acc += v;
    }
    g_dinv[i] = rsqrtf(1.0f + acc);
}

__global__ void k_w1pre(const float* __restrict__ ew) {
    int j = blockIdx.x * blockDim.x + threadIdx.x;
    if (j < NE) g_wcsr[j] = g_dinv[g_csr_src[j]] * ew[g_csr_eid[j]];
}
__global__ void k_w2pre() {
    int j = blockIdx.x * blockDim.x + threadIdx.x;
    if (j < NE) g_wcsr[j] = g_dinv[g_csr_src[j]] * g_e2[j];
}

// ---------------- CSR gather aggregation (fp16 payload, fp32 accum) ---------
// layer1 FUSED: aggregate + self + bias + relu -> out1 (g_agg1), plus ssrc/sdst.
// lane owns halves [lane*8, lane*8+8) and [(lane+32)*8, +8) of the 512-row
// = float4 indices {2*lane, 2*lane+1, 2*(lane+32), 2*(lane+32)+1}.
__global__ void k_gather1(const float* __restrict__ b1, const float* __restrict__ Wm) {
    int c = (blockIdx.x * blockDim.x + threadIdx.x) >> 5;
    int lane = threadIdx.x & 31;
    if (c >= NN) return;
    int s = g_ptr[c], e = g_ptr[c + 1];
    float4 a0 = make_float4(0, 0, 0, 0), a1 = a0, a2 = a0, a3 = a0;
    for (int j = s; j < e; j++) {
        int r = g_csr_src[j];
        float w = g_wcsr[j];
        const uint4* x = (const uint4*)(g_xw1h + (size_t)r * D1) + lane;
        uint4 u0 = x[0], u1 = x[32];
        fma8(a0, a1, u0, w);
        fma8(a2, a3, u1, w);
    }
    float dc = g_dinv[c];
    float ds = dc * dc;
    const int i0 = 2 * lane, i1 = 2 * lane + 1;
    const int i2 = 2 * (lane + 32), i3 = 2 * (lane + 32) + 1;
    const float4* xc = g_xw1 + (size_t)c * 128;
    float4 s0 = xc[i0], s1 = xc[i1], s2 = xc[i2], s3 = xc[i3];
    const float4* B1 = (const float4*)b1;
    float4 b0 = B1[i0], bb1 = B1[i1], bb2 = B1[i2], bb3 = B1[i3];

    float4 o0, o1, o2, o3;
    o0.x = fmaxf(fmaf(dc, a0.x, fmaf(ds, s0.x, b0.x)), 0.0f);
    o0.y = fmaxf(fmaf(dc, a0.y, fmaf(ds, s0.y, b0.y)), 0.0f);
    o0.z = fmaxf(fmaf(dc, a0.z, fmaf(ds, s0.z, b0.z)), 0.0f);
    o0.w = fmaxf(fmaf(dc, a0.w, fmaf(ds, s0.w, b0.w)), 0.0f);
    o1.x = fmaxf(fmaf(dc, a1.x, fmaf(ds, s1.x, bb1.x)), 0.0f);
    o1.y = fmaxf(fmaf(dc, a1.y, fmaf(ds, s1.y, bb1.y)), 0.0f);
    o1.z = fmaxf(fmaf(dc, a1.z, fmaf(ds, s1.z, bb1.z)), 0.0f);
    o1.w = fmaxf(fmaf(dc, a1.w, fmaf(ds, s1.w, bb1.w)), 0.0f);
    o2.x = fmaxf(fmaf(dc, a2.x, fmaf(ds, s2.x, bb2.x)), 0.0f);
    o2.y = fmaxf(fmaf(dc, a2.y, fmaf(ds, s2.y, bb2.y)), 0.0f);
    o2.z = fmaxf(fmaf(dc, a2.z, fmaf(ds, s2.z, bb2.z)), 0.0f);
    o2.w = fmaxf(fmaf(dc, a2.w, fmaf(ds, s2.w, bb2.w)), 0.0f);
    o3.x = fmaxf(fmaf(dc, a3.x, fmaf(ds, s3.x, bb3.x)), 0.0f);
    o3.y = fmaxf(fmaf(dc, a3.y, fmaf(ds, s3.y, bb3.y)), 0.0f);
    o3.z = fmaxf(fmaf(dc, a3.z, fmaf(ds, s3.z, bb3.z)), 0.0f);
    o3.w = fmaxf(fmaf(dc, a3.w, fmaf(ds, s3.w, bb3.w)), 0.0f);

    float4* o = g_agg1 + (size_t)c * 128;
    o[i0] = o0; o[i1] = o1; o[i2] = o2; o[i3] = o3;

    // similarity dots (same index mapping)
    const float4* WM = (const float4*)Wm;
    float4 w0 = WM[i0], w1 = WM[i1], w2 = WM[i2], w3 = WM[i3];
    float ps = o0.x * w0.x + o0.y * w0.y + o0.z * w0.z + o0.w * w0.w
             + o1.x * w1.x + o1.y * w1.y + o1.z * w1.z + o1.w * w1.w
             + o2.x * w2.x + o2.y * w2.y + o2.z * w2.z + o2.w * w2.w
             + o3.x * w3.x + o3.y * w3.y + o3.z * w3.z + o3.w * w3.w;
    w0 = WM[i0 + 128]; w1 = WM[i1 + 128]; w2 = WM[i2 + 128]; w3 = WM[i3 + 128];
    float pd = o0.x * w0.x + o0.y * w0.y + o0.z * w0.z + o0.w * w0.w
             + o1.x * w1.x + o1.y * w1.y + o1.z * w1.z + o1.w * w1.w
             + o2.x * w2.x + o2.y * w2.y + o2.z * w2.z + o2.w * w2.w
             + o3.x * w3.x + o3.y * w3.y + o3.z * w3.z + o3.w * w3.w;
    #pragma unroll
    for (int off = 16; off > 0; off >>= 1) {
        ps += __shfl_down_sync(0xffffffffu, ps, off);
        pd += __shfl_down_sync(0xffffffffu, pd, off);
    }
    if (lane == 0) {
        g_ssrc[c] = ps;
        g_sdst[c] = pd;
    }
}

// layer2: lane owns halves [lane*4, lane*4+4) = float4 index lane.
__global__ void k_gather2(const float* __restrict__ b2, float4* __restrict__ out) {
    int c = (blockIdx.x * blockDim.x + threadIdx.x) >> 5;
    int lane = threadIdx.x & 31;
    if (c >= NN) return;
    int s = g_ptr[c], e = g_ptr[c + 1];
    float4 a = make_float4(0, 0, 0, 0);
    for (int j = s; j < e; j++) {
        int r = g_csr_src[j];
        float w = g_wcsr[j];
        uint2 u = *((const uint2*)(g_xw2h + (size_t)r * D2) + lane);
        float2 p;
        p = __half22float2(*(__half2*)&u.x);
        a.x = fmaf(w, p.x, a.x); a.y = fmaf(w, p.y, a.y);
        p = __half22float2(*(__half2*)&u.y);
        a.z = fmaf(w, p.x, a.z); a.w = fmaf(w, p.y, a.w);
    }
    float dc = g_dinv[c];
    float ds = dc * dc;
    float4 sv = g_xw2[(size_t)c * 32 + lane];
    float4 bb = ((const float4*)b2)[lane];
    out[(size_t)c * 32 + lane] = make_float4(
        fmaf(dc, a.x, fmaf(ds, sv.x, bb.x)), fmaf(dc, a.y, fmaf(ds, sv.y, bb.y)),
        fmaf(dc, a.z, fmaf(ds, sv.z, bb.z)), fmaf(dc, a.w, fmaf(ds, sv.w, bb.w)));
}

// ---------------- mma.sync fp16 2-term GEMM (R8 structure) ------------------
// C(fp32) = Ah*B + Al*B; also emits fp16 copy of C for the gather payload.
// MODE 0: A = node_attr [NN,1024], B = g_w1h [1024,512], C = g_xw1 (+g_xw1h)
// MODE 1: A = g_agg1(out1) [NN,512], B = g_w2h [512,128], C = g_xw2 (+g_xw2h)
#define GBM 128
#define GBN 128
#define GBK 32
#define LDA 40    // halves, 80B stride -> conflict-free ldmatrix
#define LDB 136   // halves, 272B stride -> conflict-free ldmatrix

__device__ __forceinline__ void ldsm_x4(uint32_t* r, const __half* p) {
    uint32_t a = (uint32_t)__cvta_generic_to_shared(p);
    asm volatile("ldmatrix.sync.aligned.m8n8.x4.shared.b16 {%0,%1,%2,%3}, [%4];"
                 : "=r"(r[0]), "=r"(r[1]), "=r"(r[2]), "=r"(r[3]) : "r"(a));
}
__device__ __forceinline__ void ldsm_x2t(uint32_t* r, const __half* p) {
    uint32_t a = (uint32_t)__cvta_generic_to_shared(p);
    asm volatile("ldmatrix.sync.aligned.m8n8.x2.trans.shared.b16 {%0,%1}, [%2];"
                 : "=r"(r[0]), "=r"(r[1]) : "r"(a));
}
__device__ __forceinline__ void mma_fp16(float* c, const uint32_t* a, const uint32_t* b) {
    asm volatile(
        "mma.sync.aligned.m16n8k16.row.col.f32.f16.f16.f32 "
        "{%0,%1,%2,%3},{%4,%5,%6,%7},{%8,%9},{%0,%1,%2,%3};"
        : "+f"(c[0]), "+f"(c[1]), "+f"(c[2]), "+f"(c[3])
        : "r"(a[0]), "r"(a[1]), "r"(a[2]), "r"(a[3]), "r"(b[0]), "r"(b[1]));
}

template <int MODE>
__global__ void __launch_bounds__(256, 1) mma_gemm(const float* __restrict__ Aarg) {
    constexpr int K = (MODE == 0) ? K1 : D1;
    constexpr int N = (MODE == 0) ? D1 : D2;
    const float* __restrict__ A = (MODE == 0) ? Aarg : (const float*)g_agg1;
    const __half* __restrict__ BhG = (MODE == 0) ? g_w1h : g_w2h;
    float* __restrict__ C = (MODE == 0) ? (float*)g_xw1 : (float*)g_xw2;
    __half* __restrict__ Ch = (MODE == 0) ? g_xw1h : g_xw2h;

    __shared__ __half sAh[GBM * LDA];
    __shared__ __half sAl[GBM * LDA];
    __shared__ __half sBh[GBK * LDB];

    const int tid = threadIdx.x;
    const int lane = tid & 31;
    const int wid = tid >> 5;
    const int warp_m = wid >> 2;
    const int warp_n = wid & 3;
    const int bm0 = blockIdx.y * GBM;
    const int bn0 = blockIdx.x * GBN;

    const int arow = tid >> 2;
    const int acol = (tid & 3) * 8;
    const int brow = tid >> 4;
    const int bcol = (tid & 15) * 8;

    const bool av0 = (bm0 + arow) < NN;
    const bool av1 = (bm0 + 64 + arow) < NN;
    const size_t ar0 = (size_t)min(bm0 + arow, NN - 1);
    const size_t ar1 = (size_t)min(bm0 + 64 + arow, NN - 1);

    float acc[4][4][4];
    #pragma unroll
    for (int i = 0; i < 4; i++)
        #pragma unroll
        for (int j = 0; j < 4; j++)
            #pragma unroll
            for (int q = 0; q < 4; q++) acc[i][j][q] = 0.0f;

    float4 ra[4];
    uint4 rb[2];
    const float4 zf4 = make_float4(0, 0, 0, 0);

    {
        ra[0] = av0 ? *(const float4*)(A + ar0 * K + acol) : zf4;
        ra[1] = av0 ? *(const float4*)(A + ar0 * K + acol + 4) : zf4;
        ra[2] = av1 ? *(const float4*)(A + ar1 * K + acol) : zf4;
        ra[3] = av1 ? *(const float4*)(A + ar1 * K + acol + 4) : zf4;
        rb[0] = *(const uint4*)(BhG + (size_t)brow * N + bn0 + bcol);
        rb[1] = *(const uint4*)(BhG + (size_t)(16 + brow) * N + bn0 + bcol);
    }

    #pragma unroll 1
    for (int k0 = 0; k0 < K; k0 += GBK) {
        __syncthreads();
        {
            uint2 h0, l0, h1, l1;
            split4h(ra[0], h0, l0);
            split4h(ra[1], h1, l1);
            *(uint4*)&sAh[arow * LDA + acol] = make_uint4(h0.x, h0.y, h1.x, h1.y);
            *(uint4*)&sAl[arow * LDA + acol] = make_uint4(l0.x, l0.y, l1.x, l1.y);
            split4h(ra[2], h0, l0);
            split4h(ra[3], h1, l1);
            *(uint4*)&sAh[(arow + 64) * LDA + acol] = make_uint4(h0.x, h0.y, h1.x, h1.y);
            *(uint4*)&sAl[(arow + 64) * LDA + acol] = make_uint4(l0.x, l0.y, l1.x, l1.y);
        }
        *(uint4*)&sBh[brow * LDB + bcol] = rb[0];
        *(uint4*)&sBh[(brow + 16) * LDB + bcol] = rb[1];
        __syncthreads();

        const int kn = k0 + GBK;
        if (kn < K) {
            ra[0] = av0 ? *(const float4*)(A + ar0 * K + kn + acol) : zf4;
            ra[1] = av0 ? *(const float4*)(A + ar0 * K + kn + acol + 4) : zf4;
            ra[2] = av1 ? *(const float4*)(A + ar1 * K + kn + acol) : zf4;
            ra[3] = av1 ? *(const float4*)(A + ar1 * K + kn + acol + 4) : zf4;
            rb[0] = *(const uint4*)(BhG + (size_t)(kn + brow) * N + bn0 + bcol);
            rb[1] = *(const uint4*)(BhG + (size_t)(kn + 16 + brow) * N + bn0 + bcol);
        }

        #pragma unroll
        for (int kk = 0; kk < GBK; kk += 16) {
            uint32_t ah[4][4], al[4][4], bh[4][2];
            #pragma unroll
            for (int mt = 0; mt < 4; mt++) {
                const int mrow = warp_m * 64 + mt * 16 + (lane & 15);
                const int koff = kk + ((lane >> 4) << 3);
                ldsm_x4(ah[mt], &sAh[mrow * LDA + koff]);
                ldsm_x4(al[mt], &sAl[mrow * LDA + koff]);
            }
            #pragma unroll
            for (int nt = 0; nt < 4; nt++) {
                const int krow = kk + (lane & 15);
                const int noff = warp_n * 32 + nt * 8;
                ldsm_x2t(bh[nt], &sBh[krow * LDB + noff]);
            }
            #pragma unroll
            for (int mt = 0; mt < 4; mt++)
                #pragma unroll
                for (int nt = 0; nt < 4; nt++) {
                    mma_fp16(acc[mt][nt], ah[mt], bh[nt]);
                    mma_fp16(acc[mt][nt], al[mt], bh[nt]);
                }
        }
    }

    // epilogue: fp32 C + fp16 copy
    #pragma unroll
    for (int mt = 0; mt < 4; mt++) {
        const int r0 = bm0 + warp_m * 64 + mt * 16 + (lane >> 2);
        const int r1 = r0 + 8;
        #pragma unroll
        for (int nt = 0; nt < 4; nt++) {
            const int cc = bn0 + warp_n * 32 + nt * 8 + (lane & 3) * 2;
            if (r0 < NN) {
                *(float2*)&C[(size_t)r0 * N + cc] = make_float2(acc[mt][nt][0], acc[mt][nt][1]);
                *(__half2*)&Ch[(size_t)r0 * N + cc] =
                    __floats2half2_rn(acc[mt][nt][0], acc[mt][nt][1]);
            }
            if (r1 < NN) {
                *(float2*)&C[(size_t)r1 * N + cc] = make_float2(acc[mt][nt][2], acc[mt][nt][3]);
                *(__half2*)&Ch[(size_t)r1 * N + cc] =
                    __floats2half2_rn(acc[mt][nt][2], acc[mt][nt][3]);
            }
        }
    }
}

// ---------------- launch ----------------------------------------------------
extern "C" void kernel_launch(void* const* d_in, const int* in_sizes, int n_in,
                              void* d_out, int out_size) {
    const float* node_attr = (const float*)d_in[0];
    const float* edge_attr = (const float*)d_in[1];
    const void*  edge_index = d_in[2];
    const float* W1 = (const float*)d_in[5];
    const float* b1 = (const float*)d_in[6];
    const float* W2 = (const float*)d_in[7];
    const float* b2 = (const float*)d_in[8];
    const float* Wm = (const float*)d_in[9];
    const float* bm = (const float*)d_in[10];
    float4* out = (float4*)d_out;

    const int nodeBlocks = (NN + 255) / 256;
    const int edgeBlocks = (NE + 255) / 256;
    const int warpNodeBlocks = (NN * 32 + 255) / 256;
    const int mTiles = (NN + 127) / 128;

    // ---- edge_index convert + CSR build
    k_detect<<<1, 32>>>((const int*)edge_index);
    k_zero_cnt<<<nodeBlocks, 256>>>();
    k_convert<<<edgeBlocks, 256>>>(edge_index);
    k_scan_block<<<NB_SCAN, 256>>>();
    k_scan_bsum<<<1, 32>>>();
    k_scan_add<<<nodeBlocks, 256>>>();
    k_fill<<<edgeBlocks, 256>>>();

    // ---- weight conversions (fp32 -> fp16, small)
    k_split<1><<<((K1 * D1 / 4) + 255) / 256, 256>>>((const float4*)W1, K1 * D1 / 4);
    k_split<2><<<((D1 * D2 / 4) + 255) / 256, 256>>>((const float4*)W2, D1 * D2 / 4);

    // ---- layer 1: deg/dinv + per-slot weights
    k_deg1<<<nodeBlocks, 256>>>(edge_attr);
    k_w1pre<<<edgeBlocks, 256>>>(edge_attr);

    // ---- layer 1: xw1 = node_attr @ W1  (fp16 2-term mma, dual-precision out)
    {
        dim3 grid(D1 / GBN, mTiles);
        mma_gemm<0><<<grid, 256>>>(node_attr);
    }

    // ---- layer 1: CSR gather (fp16 payload) + self + bias + relu + similarity
    k_gather1<<<warpNodeBlocks, 256>>>(b1, Wm);

    // ---- layer 2: e2 + deg/dinv + weights
    k_deg2<<<nodeBlocks, 256>>>(bm);
    k_w2pre<<<edgeBlocks, 256>>>();

    // ---- layer 2: xw2 = out1 @ W2  (fp16 2-term mma, dual-precision out)
    {
        dim3 grid(D2 / GBN, mTiles);
        mma_gemm<1><<<grid, 256>>>(nullptr);
    }

    // ---- layer 2: CSR gather (fp16 payload) into output (+ bias, self)
    k_gather2<<<warpNodeBlocks, 256>>>(b2, out);

    (void)in_sizes; (void)n_in; (void)out_size;
}

// round 15
// speedup vs baseline: 1.6642x; 1.2747x over previous
#include <cuda_runtime.h>
#include <cuda_fp16.h>
#include <cstddef>
#include <cstdint>

#define NN 100000
#define NE 1600000
#define D1 512      // hidden dim (layer1 out)
#define D2 128      // output dim
#define K1 1024     // input dim
#define NB_SCAN ((NN + 255) / 256)

// ---------------- scratch (static device globals; referenced ONLY from device code) ---
// All activations live in fp16; accumulation is fp32 in registers.
__device__ __half g_xw1h[(size_t)NN * D1];      // x @ W1 (fp16)
__device__ __half g_o1h[(size_t)NN * D1];       // out1 = relu(agg+b1) (fp16)
__device__ __half g_xw2h[(size_t)NN * D2];      // out1 @ W2 (fp16)
__device__ float  g_dinv[NN];
__device__ float  g_ssrc[NN];
__device__ float  g_sdst[NN];
__device__ int    g_row[NE];
__device__ int    g_col[NE];
__device__ int    g_is64;

// CSR (grouped by destination col)
__device__ int    g_cnt[NN];
__device__ int    g_ptr[NN + 1];
__device__ int    g_cur[NN];
__device__ int    g_bsum[NB_SCAN];
__device__ int    g_boff[NB_SCAN];
__device__ int    g_csr_src[NE];
__device__ int    g_csr_eid[NE];
__device__ float  g_wcsr[NE];
__device__ float  g_e2[NE];

// fp16 weights
__device__ __half g_w1h[(size_t)K1 * D1];
__device__ __half g_w2h[(size_t)D1 * D2];

// ---------------- helpers ---------------------------------------------------
__device__ __forceinline__ uint4 cvt8(float4 a, float4 b) {
    uint4 u;
    *(__half2*)&u.x = __floats2half2_rn(a.x, a.y);
    *(__half2*)&u.y = __floats2half2_rn(a.z, a.w);
    *(__half2*)&u.z = __floats2half2_rn(b.x, b.y);
    *(__half2*)&u.w = __floats2half2_rn(b.z, b.w);
    return u;
}
__device__ __forceinline__ void h8f(uint4 u, float4& A, float4& B) {
    float2 p;
    p = __half22float2(*(__half2*)&u.x); A.x = p.x; A.y = p.y;
    p = __half22float2(*(__half2*)&u.y); A.z = p.x; A.w = p.y;
    p = __half22float2(*(__half2*)&u.z); B.x = p.x; B.y = p.y;
    p = __half22float2(*(__half2*)&u.w); B.z = p.x; B.w = p.y;
}
// fma 8 halves (one uint4) into two float4 accumulators
__device__ __forceinline__ void fma8(float4& A, float4& B, uint4 u, float w) {
    float2 p;
    p = __half22float2(*(__half2*)&u.x); A.x = fmaf(w, p.x, A.x); A.y = fmaf(w, p.y, A.y);
    p = __half22float2(*(__half2*)&u.y); A.z = fmaf(w, p.x, A.z); A.w = fmaf(w, p.y, A.w);
    p = __half22float2(*(__half2*)&u.z); B.x = fmaf(w, p.x, B.x); B.y = fmaf(w, p.y, B.y);
    p = __half22float2(*(__half2*)&u.w); B.z = fmaf(w, p.x, B.z); B.w = fmaf(w, p.y, B.w);
}

// WHICH 1: W1 -> g_w1h ; 2: W2 -> g_w2h   (fp32 -> fp16)
template <int WHICH>
__global__ void k_split(const float4* __restrict__ src, int n4) {
    int idx = blockIdx.x * blockDim.x + threadIdx.x;
    if (idx >= n4) return;
    __half* Dh = (WHICH == 1) ? g_w1h : g_w2h;
    float4 v = src[idx];
    uint2 p;
    p.x = ((uint32_t)__half_as_ushort(__float2half_rn(v.y)) << 16) |
          __half_as_ushort(__float2half_rn(v.x));
    p.y = ((uint32_t)__half_as_ushort(__float2half_rn(v.w)) << 16) |
          __half_as_ushort(__float2half_rn(v.z));
    ((uint2*)Dh)[idx] = p;
}

// ---------------- edge_index dtype detect + convert + histogram ------------
__global__ void k_detect(const int* __restrict__ ei32) {
    if (blockIdx.x != 0 || threadIdx.x != 0) return;
    int is64 = 1;
    for (int i = 1; i < 512; i += 2) {
        if (ei32[i] != 0) { is64 = 0; break; }
    }
    g_is64 = is64;
}

__global__ void k_zero_cnt() {
    int i = blockIdx.x * blockDim.x + threadIdx.x;
    if (i < NN) g_cnt[i] = 0;
}

__global__ void k_convert(const void* __restrict__ ei) {
    int e = blockIdx.x * blockDim.x + threadIdx.x;
    if (e >= NE) return;
    int r, c;
    if (g_is64) {
        const long long* p = (const long long*)ei;
        r = (int)p[e];
        c = (int)p[NE + e];
    } else {
        const int* p = (const int*)ei;
        r = p[e];
        c = p[NE + e];
    }
    g_row[e] = r;
    g_col[e] = c;
    atomicAdd(&g_cnt[c], 1);
}

// ---------------- exclusive scan of g_cnt -> g_ptr --------------------------
__global__ void k_scan_block() {
    __shared__ int sh[256];
    int i = blockIdx.x * 256 + threadIdx.x;
    int v = (i < NN) ? g_cnt[i] : 0;
    sh[threadIdx.x] = v;
    __syncthreads();
    #pragma unroll
    for (int o = 1; o < 256; o <<= 1) {
        int t = (threadIdx.x >= o) ? sh[threadIdx.x - o] : 0;
        __syncthreads();
        sh[threadIdx.x] += t;
        __syncthreads();
    }
    if (i < NN) g_ptr[i] = sh[threadIdx.x] - v;
    if (threadIdx.x == 255) g_bsum[blockIdx.x] = sh[255];
}

__global__ void k_scan_bsum() {
    if (blockIdx.x != 0 || threadIdx.x != 0) return;
    int run = 0;
    for (int b = 0; b < NB_SCAN; b++) {
        g_boff[b] = run;
        run += g_bsum[b];
    }
}

__global__ void k_scan_add() {
    int i = blockIdx.x * blockDim.x + threadIdx.x;
    if (i < NN) {
        int p = g_ptr[i] + g_boff[i >> 8];
        g_ptr[i] = p;
        g_cur[i] = p;
    }
    if (i == 0) g_ptr[NN] = NE;
}

__global__ void k_fill() {
    int e = blockIdx.x * blockDim.x + threadIdx.x;
    if (e >= NE) return;
    int c = g_col[e];
    int pos = atomicAdd(&g_cur[c], 1);
    g_csr_src[pos] = g_row[e];
    g_csr_eid[pos] = e;
}

// ---------------- per-node degree / dinv (atomic-free via CSR) --------------
__global__ void k_deg1(const float* __restrict__ ew) {
    int i = blockIdx.x * blockDim.x + threadIdx.x;
    if (i >= NN) return;
    int s = g_ptr[i], e = g_ptr[i + 1];
    float acc = 0.0f;
    for (int j = s; j < e; j++) acc += ew[g_csr_eid[j]];
    g_dinv[i] = rsqrtf(1.0f + acc);
}

__global__ void k_deg2(const float* __restrict__ bm) {
    int i = blockIdx.x * blockDim.x + threadIdx.x;
    if (i >= NN) return;
    int s = g_ptr[i], e = g_ptr[i + 1];
    float sd = g_sdst[i] + bm[0];
    float acc = 0.0f;
    for (int j = s; j < e; j++) {
        float v = fmaxf(g_ssrc[g_csr_src[j]] + sd, 0.0f);
        g_e2[j] = v;
        acc += v;
    }
    g_dinv[i] = rsqrtf(1.0f + acc);
}

__global__ void k_w1pre(const float* __restrict__ ew) {
    int j = blockIdx.x * blockDim.x + threadIdx.x;
    if (j < NE) g_wcsr[j] = g_dinv[g_csr_src[j]] * ew[g_csr_eid[j]];
}
__global__ void k_w2pre() {
    int j = blockIdx.x * blockDim.x + threadIdx.x;
    if (j < NE) g_wcsr[j] = g_dinv[g_csr_src[j]] * g_e2[j];
}

// ---------------- CSR gather aggregation (fp16 payload, fp32 accum) ---------
// layer1 FUSED: aggregate + self + bias + relu -> out1 (g_o1h fp16), + ssrc/sdst.
// lane owns halves [lane*8,+8) and [(lane+32)*8,+8)  (uint4 idx lane, lane+32)
__global__ void k_gather1(const float* __restrict__ b1, const float* __restrict__ Wm) {
    int c = (blockIdx.x * blockDim.x + threadIdx.x) >> 5;
    int lane = threadIdx.x & 31;
    if (c >= NN) return;
    int s = g_ptr[c], e = g_ptr[c + 1];
    float4 a0 = make_float4(0, 0, 0, 0), a1 = a0, a2 = a0, a3 = a0;
    for (int j = s; j < e; j++) {
        int r = g_csr_src[j];
        float w = g_wcsr[j];
        const uint4* x = (const uint4*)(g_xw1h + (size_t)r * D1) + lane;
        uint4 u0 = x[0], u1 = x[32];
        fma8(a0, a1, u0, w);
        fma8(a2, a3, u1, w);
    }
    float dc = g_dinv[c];
    float ds = dc * dc;
    const int i0 = 2 * lane, i1 = 2 * lane + 1;
    const int i2 = 2 * (lane + 32), i3 = 2 * (lane + 32) + 1;
    const uint4* xc = (const uint4*)(g_xw1h + (size_t)c * D1) + lane;
    float4 s0, s1, s2, s3;
    h8f(xc[0], s0, s1);
    h8f(xc[32], s2, s3);
    const float4* B1 = (const float4*)b1;
    float4 b0 = B1[i0], bb1 = B1[i1], bb2 = B1[i2], bb3 = B1[i3];

    float4 o0, o1, o2, o3;
    o0.x = fmaxf(fmaf(dc, a0.x, fmaf(ds, s0.x, b0.x)), 0.0f);
    o0.y = fmaxf(fmaf(dc, a0.y, fmaf(ds, s0.y, b0.y)), 0.0f);
    o0.z = fmaxf(fmaf(dc, a0.z, fmaf(ds, s0.z, b0.z)), 0.0f);
    o0.w = fmaxf(fmaf(dc, a0.w, fmaf(ds, s0.w, b0.w)), 0.0f);
    o1.x = fmaxf(fmaf(dc, a1.x, fmaf(ds, s1.x, bb1.x)), 0.0f);
    o1.y = fmaxf(fmaf(dc, a1.y, fmaf(ds, s1.y, bb1.y)), 0.0f);
    o1.z = fmaxf(fmaf(dc, a1.z, fmaf(ds, s1.z, bb1.z)), 0.0f);
    o1.w = fmaxf(fmaf(dc, a1.w, fmaf(ds, s1.w, bb1.w)), 0.0f);
    o2.x = fmaxf(fmaf(dc, a2.x, fmaf(ds, s2.x, bb2.x)), 0.0f);
    o2.y = fmaxf(fmaf(dc, a2.y, fmaf(ds, s2.y, bb2.y)), 0.0f);
    o2.z = fmaxf(fmaf(dc, a2.z, fmaf(ds, s2.z, bb2.z)), 0.0f);
    o2.w = fmaxf(fmaf(dc, a2.w, fmaf(ds, s2.w, bb2.w)), 0.0f);
    o3.x = fmaxf(fmaf(dc, a3.x, fmaf(ds, s3.x, bb3.x)), 0.0f);
    o3.y = fmaxf(fmaf(dc, a3.y, fmaf(ds, s3.y, bb3.y)), 0.0f);
    o3.z = fmaxf(fmaf(dc, a3.z, fmaf(ds, s3.z, bb3.z)), 0.0f);
    o3.w = fmaxf(fmaf(dc, a3.w, fmaf(ds, s3.w, bb3.w)), 0.0f);

    uint4* o = (uint4*)(g_o1h + (size_t)c * D1) + lane;
    o[0]  = cvt8(o0, o1);
    o[32] = cvt8(o2, o3);

    // similarity dots (fp32, pre-rounding)
    const float4* WM = (const float4*)Wm;
    float4 w0 = WM[i0], w1 = WM[i1], w2 = WM[i2], w3 = WM[i3];
    float ps = o0.x * w0.x + o0.y * w0.y + o0.z * w0.z + o0.w * w0.w
             + o1.x * w1.x + o1.y * w1.y + o1.z * w1.z + o1.w * w1.w
             + o2.x * w2.x + o2.y * w2.y + o2.z * w2.z + o2.w * w2.w
             + o3.x * w3.x + o3.y * w3.y + o3.z * w3.z + o3.w * w3.w;
    w0 = WM[i0 + 128]; w1 = WM[i1 + 128]; w2 = WM[i2 + 128]; w3 = WM[i3 + 128];
    float pd = o0.x * w0.x + o0.y * w0.y + o0.z * w0.z + o0.w * w0.w
             + o1.x * w1.x + o1.y * w1.y + o1.z * w1.z + o1.w * w1.w
             + o2.x * w2.x + o2.y * w2.y + o2.z * w2.z + o2.w * w2.w
             + o3.x * w3.x + o3.y * w3.y + o3.z * w3.z + o3.w * w3.w;
    #pragma unroll
    for (int off = 16; off > 0; off >>= 1) {
        ps += __shfl_down_sync(0xffffffffu, ps, off);
        pd += __shfl_down_sync(0xffffffffu, pd, off);
    }
    if (lane == 0) {
        g_ssrc[c] = ps;
        g_sdst[c] = pd;
    }
}

// layer2: lane owns halves [lane*4,+4) (uint2 idx lane); output fp32 + bias.
__global__ void k_gather2(const float* __restrict__ b2, float4* __restrict__ out) {
    int c = (blockIdx.x * blockDim.x + threadIdx.x) >> 5;
    int lane = threadIdx.x & 31;
    if (c >= NN) return;
    int s = g_ptr[c], e = g_ptr[c + 1];
    float4 a = make_float4(0, 0, 0, 0);
    for (int j = s; j < e; j++) {
        int r = g_csr_src[j];
        float w = g_wcsr[j];
        uint2 u = *((const uint2*)(g_xw2h + (size_t)r * D2) + lane);
        float2 p;
        p = __half22float2(*(__half2*)&u.x);
        a.x = fmaf(w, p.x, a.x); a.y = fmaf(w, p.y, a.y);
        p = __half22float2(*(__half2*)&u.y);
        a.z = fmaf(w, p.x, a.z); a.w = fmaf(w, p.y, a.w);
    }
    float dc = g_dinv[c];
    float ds = dc * dc;
    uint2 us = *((const uint2*)(g_xw2h + (size_t)c * D2) + lane);
    float2 p0 = __half22float2(*(__half2*)&us.x);
    float2 p1 = __half22float2(*(__half2*)&us.y);
    float4 bb = ((const float4*)b2)[lane];
    out[(size_t)c * 32 + lane] = make_float4(
        fmaf(dc, a.x, fmaf(ds, p0.x, bb.x)), fmaf(dc, a.y, fmaf(ds, p0.y, bb.y)),
        fmaf(dc, a.z, fmaf(ds, p1.x, bb.z)), fmaf(dc, a.w, fmaf(ds, p1.y, bb.w)));
}

// ---------------- mma.sync fp16 single-term GEMM ----------------------------
// C(fp16) = A(fp16) * B(fp16), fp32 accumulate; epilogue writes fp16 only.
// MODE 0: A = node_attr fp32 (convert in-flight), B = g_w1h, C = g_xw1h
// MODE 1: A = g_o1h fp16 (direct),                B = g_w2h, C = g_xw2h
#define GBM 128
#define GBN 128
#define GBK 32
#define LDA 40    // halves, 80B stride -> conflict-free ldmatrix
#define LDB 136   // halves, 272B stride -> conflict-free ldmatrix

__device__ __forceinline__ void ldsm_x4(uint32_t* r, const __half* p) {
    uint32_t a = (uint32_t)__cvta_generic_to_shared(p);
    asm volatile("ldmatrix.sync.aligned.m8n8.x4.shared.b16 {%0,%1,%2,%3}, [%4];"
                 : "=r"(r[0]), "=r"(r[1]), "=r"(r[2]), "=r"(r[3]) : "r"(a));
}
__device__ __forceinline__ void ldsm_x2t(uint32_t* r, const __half* p) {
    uint32_t a = (uint32_t)__cvta_generic_to_shared(p);
    asm volatile("ldmatrix.sync.aligned.m8n8.x2.trans.shared.b16 {%0,%1}, [%2];"
                 : "=r"(r[0]), "=r"(r[1]) : "r"(a));
}
__device__ __forceinline__ void mma_fp16(float* c, const uint32_t* a, const uint32_t* b) {
    asm volatile(
        "mma.sync.aligned.m16n8k16.row.col.f32.f16.f16.f32 "
        "{%0,%1,%2,%3},{%4,%5,%6,%7},{%8,%9},{%0,%1,%2,%3};"
        : "+f"(c[0]), "+f"(c[1]), "+f"(c[2]), "+f"(c[3])
        : "r"(a[0]), "r"(a[1]), "r"(a[2]), "r"(a[3]), "r"(b[0]), "r"(b[1]));
}

template <int MODE>
__global__ void __launch_bounds__(256, 1) mma_gemm(const float* __restrict__ Aarg) {
    constexpr int K = (MODE == 0) ? K1 : D1;
    constexpr int N = (MODE == 0) ? D1 : D2;
    const __half* __restrict__ BhG = (MODE == 0) ? g_w1h : g_w2h;
    __half* __restrict__ Ch = (MODE == 0) ? g_xw1h : g_xw2h;

    __shared__ __half sAh[GBM * LDA];
    __shared__ __half sBh[GBK * LDB];

    const int tid = threadIdx.x;
    const int lane = tid & 31;
    const int wid = tid >> 5;
    const int warp_m = wid >> 2;
    const int warp_n = wid & 3;
    const int bm0 = blockIdx.y * GBM;
    const int bn0 = blockIdx.x * GBN;

    const int arow = tid >> 2;             // 0..63 (two halves: +0, +64)
    const int acol = (tid & 3) * 8;        // halves: 0,8,16,24
    const int brow = tid >> 4;
    const int bcol = (tid & 15) * 8;

    const bool av0 = (bm0 + arow) < NN;
    const bool av1 = (bm0 + 64 + arow) < NN;
    const size_t ar0 = (size_t)min(bm0 + arow, NN - 1);
    const size_t ar1 = (size_t)min(bm0 + 64 + arow, NN - 1);

    float acc[4][4][4];
    #pragma unroll
    for (int i = 0; i < 4; i++)
        #pragma unroll
        for (int j = 0; j < 4; j++)
            #pragma unroll
            for (int q = 0; q < 4; q++) acc[i][j][q] = 0.0f;

    float4 raf[4];                         // MODE 0
    uint4 rah[2];                          // MODE 1
    const float4 zf4 = make_float4(0, 0, 0, 0);
    const uint4 zu4 = make_uint4(0, 0, 0, 0);

    // prefetch k0 = 0
    if (MODE == 0) {
        raf[0] = av0 ? *(const float4*)(Aarg + ar0 * K + acol) : zf4;
        raf[1] = av0 ? *(const float4*)(Aarg + ar0 * K + acol + 4) : zf4;
        raf[2] = av1 ? *(const float4*)(Aarg + ar1 * K + acol) : zf4;
        raf[3] = av1 ? *(const float4*)(Aarg + ar1 * K + acol + 4) : zf4;
    } else {
        rah[0] = av0 ? *(const uint4*)(g_o1h + ar0 * K + acol) : zu4;
        rah[1] = av1 ? *(const uint4*)(g_o1h + ar1 * K + acol) : zu4;
    }
    uint4 rb[2];
    rb[0] = *(const uint4*)(BhG + (size_t)brow * N + bn0 + bcol);
    rb[1] = *(const uint4*)(BhG + (size_t)(16 + brow) * N + bn0 + bcol);

    #pragma unroll 1
    for (int k0 = 0; k0 < K; k0 += GBK) {
        __syncthreads();
        if (MODE == 0) {
            *(uint4*)&sAh[arow * LDA + acol] = cvt8(raf[0], raf[1]);
            *(uint4*)&sAh[(arow + 64) * LDA + acol] = cvt8(raf[2], raf[3]);
        } else {
            *(uint4*)&sAh[arow * LDA + acol] = rah[0];
            *(uint4*)&sAh[(arow + 64) * LDA + acol] = rah[1];
        }
        *(uint4*)&sBh[brow * LDB + bcol] = rb[0];
        *(uint4*)&sBh[(brow + 16) * LDB + bcol] = rb[1];
        __syncthreads();

        const int kn = k0 + GBK;
        if (kn < K) {
            if (MODE == 0) {
                raf[0] = av0 ? *(const float4*)(Aarg + ar0 * K + kn + acol) : zf4;
                raf[1] = av0 ? *(const float4*)(Aarg + ar0 * K + kn + acol + 4) : zf4;
                raf[2] = av1 ? *(const float4*)(Aarg + ar1 * K + kn + acol) : zf4;
                raf[3] = av1 ? *(const float4*)(Aarg + ar1 * K + kn + acol + 4) : zf4;
            } else {
                rah[0] = av0 ? *(const uint4*)(g_o1h + ar0 * K + kn + acol) : zu4;
                rah[1] = av1 ? *(const uint4*)(g_o1h + ar1 * K + kn + acol) : zu4;
            }
            rb[0] = *(const uint4*)(BhG + (size_t)(kn + brow) * N + bn0 + bcol);
            rb[1] = *(const uint4*)(BhG + (size_t)(kn + 16 + brow) * N + bn0 + bcol);
        }

        #pragma unroll
        for (int kk = 0; kk < GBK; kk += 16) {
            uint32_t ah[4][4], bh[4][2];
            #pragma unroll
            for (int mt = 0; mt < 4; mt++) {
                const int mrow = warp_m * 64 + mt * 16 + (lane & 15);
                const int koff = kk + ((lane >> 4) << 3);
                ldsm_x4(ah[mt], &sAh[mrow * LDA + koff]);
            }
            #pragma unroll
            for (int nt = 0; nt < 4; nt++) {
                const int krow = kk + (lane & 15);
                const int noff = warp_n * 32 + nt * 8;
                ldsm_x2t(bh[nt], &sBh[krow * LDB + noff]);
            }
            #pragma unroll
            for (int mt = 0; mt < 4; mt++)
                #pragma unroll
                for (int nt = 0; nt < 4; nt++)
                    mma_fp16(acc[mt][nt], ah[mt], bh[nt]);
        }
    }

    // epilogue: fp16 only
    #pragma unroll
    for (int mt = 0; mt < 4; mt++) {
        const int r0 = bm0 + warp_m * 64 + mt * 16 + (lane >> 2);
        const int r1 = r0 + 8;
        #pragma unroll
        for (int nt = 0; nt < 4; nt++) {
            const int cc = bn0 + warp_n * 32 + nt * 8 + (lane & 3) * 2;
            if (r0 < NN)
                *(__half2*)&Ch[(size_t)r0 * N + cc] =
                    __floats2half2_rn(acc[mt][nt][0], acc[mt][nt][1]);
            if (r1 < NN)
                *(__half2*)&Ch[(size_t)r1 * N + cc] =
                    __floats2half2_rn(acc[mt][nt][2], acc[mt][nt][3]);
        }
    }
}

// ---------------- launch ----------------------------------------------------
extern "C" void kernel_launch(void* const* d_in, const int* in_sizes, int n_in,
                              void* d_out, int out_size) {
    const float* node_attr = (const float*)d_in[0];
    const float* edge_attr = (const float*)d_in[1];
    const void*  edge_index = d_in[2];
    const float* W1 = (const float*)d_in[5];
    const float* b1 = (const float*)d_in[6];
    const float* W2 = (const float*)d_in[7];
    const float* b2 = (const float*)d_in[8];
    const float* Wm = (const float*)d_in[9];
    const float* bm = (const float*)d_in[10];
    float4* out = (float4*)d_out;

    const int nodeBlocks = (NN + 255) / 256;
    const int edgeBlocks = (NE + 255) / 256;
    const int warpNodeBlocks = (NN * 32 + 255) / 256;
    const int mTiles = (NN + 127) / 128;

    // ---- edge_index convert + CSR build
    k_detect<<<1, 32>>>((const int*)edge_index);
    k_zero_cnt<<<nodeBlocks, 256>>>();
    k_convert<<<edgeBlocks, 256>>>(edge_index);
    k_scan_block<<<NB_SCAN, 256>>>();
    k_scan_bsum<<<1, 32>>>();
    k_scan_add<<<nodeBlocks, 256>>>();
    k_fill<<<edgeBlocks, 256>>>();

    // ---- weight conversions (fp32 -> fp16, small)
    k_split<1><<<((K1 * D1 / 4) + 255) / 256, 256>>>((const float4*)W1, K1 * D1 / 4);
    k_split<2><<<((D1 * D2 / 4) + 255) / 256, 256>>>((const float4*)W2, D1 * D2 / 4);

    // ---- layer 1: deg/dinv + per-slot weights
    k_deg1<<<nodeBlocks, 256>>>(edge_attr);
    k_w1pre<<<edgeBlocks, 256>>>(edge_attr);

    // ---- layer 1: xw1 = node_attr @ W1 (fp16 single-term mma)
    {
        dim3 grid(D1 / GBN, mTiles);
        mma_gemm<0><<<grid, 256>>>(node_attr);
    }

    // ---- layer 1: CSR gather (fp16) + self + bias + relu + similarity (FUSED)
    k_gather1<<<warpNodeBlocks, 256>>>(b1, Wm);

    // ---- layer 2: e2 + deg/dinv + weights
    k_deg2<<<nodeBlocks, 256>>>(bm);
    k_w2pre<<<edgeBlocks, 256>>>();

    // ---- layer 2: xw2 = out1 @ W2 (fp16 single-term mma)
    {
        dim3 grid(D2 / GBN, mTiles);
        mma_gemm<1><<<grid, 256>>>(nullptr);
    }

    // ---- layer 2: CSR gather (fp16) into output (+ bias, self)
    k_gather2<<<warpNodeBlocks, 256>>>(b2, out);

    (void)in_sizes; (void)n_in; (void)out_size;
}